// round 1
// baseline (speedup 1.0000x reference)
#include <cuda_runtime.h>
#include <cuda_bf16.h>
#include <math.h>

// Problem constants
#define BB   8
#define NN   1024
#define DIM  768
#define NH   12
#define HD   64
#define SCALE 0.125f   // HD^-0.5

#define M_TOTAL (BB*NN)          // 8192
#define KV_N    (2*DIM)          // 1536

// Scratch (device globals: allocation-free per harness rules)
__device__ float g_kv[M_TOTAL * KV_N];   // [B*N, 1536]
__device__ float g_wa[M_TOTAL * DIM];    // [B*N, 768]

// ---------------------------------------------------------------------------
// GEMM + bias: C[M,N] = A[M,K] @ W[K,N] + bias[N]
// 128x128 block tile, BK=16, 256 threads, 8x8 micro-tile.
// M % 128 == 0, N % 128 == 0, K % 16 == 0 guaranteed by problem sizes.
// ---------------------------------------------------------------------------
__global__ __launch_bounds__(256)
void gemm_bias_kernel(const float* __restrict__ A, const float* __restrict__ W,
                      const float* __restrict__ bias, float* __restrict__ C,
                      int M, int N, int K)
{
    __shared__ float AsT[16][132];   // A^T tile: [k][m], padded (132%4==0)
    __shared__ float Bs[16][132];    // B tile:   [k][n]

    const int tid = threadIdx.x;
    const int ty = tid >> 4;         // 0..15 -> rows ty*8
    const int tx = tid & 15;         // 0..15 -> cols tx*8
    const int m0 = blockIdx.y * 128;
    const int n0 = blockIdx.x * 128;

    float acc[8][8];
#pragma unroll
    for (int i = 0; i < 8; i++)
#pragma unroll
        for (int j = 0; j < 8; j++) acc[i][j] = 0.f;

    for (int k0 = 0; k0 < K; k0 += 16) {
        // Load A tile (128 rows x 16 k) = 512 float4, 2 per thread
#pragma unroll
        for (int i = 0; i < 2; i++) {
            int idx = tid + i * 256;
            int m  = idx >> 2;       // 0..127
            int kq = idx & 3;        // 0..3
            float4 a4 = *(const float4*)(A + (size_t)(m0 + m) * K + k0 + kq * 4);
            AsT[kq*4+0][m] = a4.x;
            AsT[kq*4+1][m] = a4.y;
            AsT[kq*4+2][m] = a4.z;
            AsT[kq*4+3][m] = a4.w;
        }
        // Load B tile (16 k x 128 n) = 512 float4, 2 per thread
#pragma unroll
        for (int i = 0; i < 2; i++) {
            int idx = tid + i * 256;
            int k  = idx >> 5;       // 0..15
            int nq = idx & 31;       // 0..31
            float4 b4 = *(const float4*)(W + (size_t)(k0 + k) * N + n0 + nq * 4);
            *(float4*)&Bs[k][nq * 4] = b4;
        }
        __syncthreads();

#pragma unroll
        for (int k = 0; k < 16; k++) {
            float4 a0 = *(float4*)&AsT[k][ty * 8];
            float4 a1 = *(float4*)&AsT[k][ty * 8 + 4];
            float4 b0 = *(float4*)&Bs[k][tx * 8];
            float4 b1 = *(float4*)&Bs[k][tx * 8 + 4];
            float ar[8] = {a0.x, a0.y, a0.z, a0.w, a1.x, a1.y, a1.z, a1.w};
            float br[8] = {b0.x, b0.y, b0.z, b0.w, b1.x, b1.y, b1.z, b1.w};
#pragma unroll
            for (int i = 0; i < 8; i++)
#pragma unroll
                for (int j = 0; j < 8; j++)
                    acc[i][j] = fmaf(ar[i], br[j], acc[i][j]);
        }
        __syncthreads();
    }

    // Epilogue: add bias, store
    float bv[8];
#pragma unroll
    for (int j = 0; j < 8; j++) bv[j] = bias[n0 + tx * 8 + j];
#pragma unroll
    for (int i = 0; i < 8; i++) {
        float* crow = C + (size_t)(m0 + ty * 8 + i) * N + n0 + tx * 8;
        float4 c0 = make_float4(acc[i][0] + bv[0], acc[i][1] + bv[1],
                                acc[i][2] + bv[2], acc[i][3] + bv[3]);
        float4 c1 = make_float4(acc[i][4] + bv[4], acc[i][5] + bv[5],
                                acc[i][6] + bv[6], acc[i][7] + bv[7]);
        *(float4*)(crow)     = c0;
        *(float4*)(crow + 4) = c1;
    }
}

// ---------------------------------------------------------------------------
// Fused attention: per block = one (b, h, 128-query tile).
// Q tile [128,64] in smem (transposed), stream K/V tiles of 64, online
// softmax, O accumulator in registers, output written in [B,N,DIM] layout.
// Dynamic smem: QsT 64x132 + KsT 64x68 + Vs 64x68 + PsT 64x132 = 102400 B.
// ---------------------------------------------------------------------------
#define ATTN_SMEM_BYTES 102400

__global__ __launch_bounds__(256)
void attn_kernel(const float* __restrict__ dec, const float* __restrict__ kv,
                 float* __restrict__ wa)
{
    extern __shared__ float sm[];
    float* QsT = sm;                       // [64][132]  Q^T: [d][r]
    float* KsT = QsT + 64 * 132;           // [64][68]   K^T: [d][j]
    float* Vs  = KsT + 64 * 68;            // [64][68]   V:   [j][d]
    float* PsT = Vs  + 64 * 68;            // [64][132]  P^T: [j][r]

    const int b  = blockIdx.z;
    const int h  = blockIdx.y;
    const int qt = blockIdx.x;             // 0..7 (128 queries each)
    const int tid = threadIdx.x;
    const int ty = tid >> 4;               // 0..15 -> q rows ty*8..+7
    const int tx = tid & 15;               // 0..15 -> key cols / out dims tx*4..+3

    // Load Q tile transposed: QsT[d][r]
    {
        const float* qbase = dec + (size_t)(b * NN + qt * 128) * DIM + h * HD;
#pragma unroll
        for (int i = 0; i < 8; i++) {
            int idx = tid + i * 256;
            int r  = idx >> 4;             // 0..127
            int dq = idx & 15;             // 0..15
            float4 q4 = *(const float4*)(qbase + (size_t)r * DIM + dq * 4);
            QsT[(dq*4+0) * 132 + r] = q4.x;
            QsT[(dq*4+1) * 132 + r] = q4.y;
            QsT[(dq*4+2) * 132 + r] = q4.z;
            QsT[(dq*4+3) * 132 + r] = q4.w;
        }
    }

    float acc[8][4];
    float m_run[8], l_run[8];
#pragma unroll
    for (int i = 0; i < 8; i++) {
        m_run[i] = -1e30f;
        l_run[i] = 0.f;
#pragma unroll
        for (int c = 0; c < 4; c++) acc[i][c] = 0.f;
    }

    const float* kbase = kv + (size_t)b * NN * KV_N + h * HD;
    const float* vbase = kbase + DIM;

    for (int kt = 0; kt < NN / 64; kt++) {
        __syncthreads();   // previous PV done; Q visible (first iter)

        // Load K tile transposed + V tile (64 rows x 64 d each)
#pragma unroll
        for (int i = 0; i < 4; i++) {
            int idx = tid + i * 256;
            int j  = idx >> 4;             // 0..63
            int dq = idx & 15;             // 0..15
            const float* kp = kbase + (size_t)(kt * 64 + j) * KV_N + dq * 4;
            float4 k4 = *(const float4*)kp;
            KsT[(dq*4+0) * 68 + j] = k4.x;
            KsT[(dq*4+1) * 68 + j] = k4.y;
            KsT[(dq*4+2) * 68 + j] = k4.z;
            KsT[(dq*4+3) * 68 + j] = k4.w;
            float4 v4 = *(const float4*)(vbase + (size_t)(kt * 64 + j) * KV_N + dq * 4);
            *(float4*)&Vs[j * 68 + dq * 4] = v4;
        }
        __syncthreads();

        // S = Q @ K^T  (8 rows x 4 cols per thread)
        float s[8][4];
#pragma unroll
        for (int i = 0; i < 8; i++)
#pragma unroll
            for (int c = 0; c < 4; c++) s[i][c] = 0.f;

#pragma unroll 8
        for (int d = 0; d < 64; d++) {
            float4 a0 = *(float4*)&QsT[d * 132 + ty * 8];
            float4 a1 = *(float4*)&QsT[d * 132 + ty * 8 + 4];
            float4 b0 = *(float4*)&KsT[d * 68 + tx * 4];
            float ar[8] = {a0.x, a0.y, a0.z, a0.w, a1.x, a1.y, a1.z, a1.w};
            float br[4] = {b0.x, b0.y, b0.z, b0.w};
#pragma unroll
            for (int i = 0; i < 8; i++)
#pragma unroll
                for (int c = 0; c < 4; c++)
                    s[i][c] = fmaf(ar[i], br[c], s[i][c]);
        }

        // Online softmax (rows reduced across the 16 tx lanes)
#pragma unroll
        for (int i = 0; i < 8; i++) {
#pragma unroll
            for (int c = 0; c < 4; c++) s[i][c] *= SCALE;
            float mx = fmaxf(fmaxf(s[i][0], s[i][1]), fmaxf(s[i][2], s[i][3]));
#pragma unroll
            for (int off = 8; off >= 1; off >>= 1)
                mx = fmaxf(mx, __shfl_xor_sync(0xffffffffu, mx, off));
            float newm = fmaxf(m_run[i], mx);
            float alpha = __expf(m_run[i] - newm);
            m_run[i] = newm;
            float rsum = 0.f;
#pragma unroll
            for (int c = 0; c < 4; c++) {
                float p = __expf(s[i][c] - newm);
                rsum += p;
                PsT[(tx * 4 + c) * 132 + ty * 8 + i] = p;
            }
#pragma unroll
            for (int off = 8; off >= 1; off >>= 1)
                rsum += __shfl_xor_sync(0xffffffffu, rsum, off);
            l_run[i] = l_run[i] * alpha + rsum;
#pragma unroll
            for (int c = 0; c < 4; c++) acc[i][c] *= alpha;
        }
        __syncthreads();

        // O += P @ V
#pragma unroll 8
        for (int j = 0; j < 64; j++) {
            float4 p0 = *(float4*)&PsT[j * 132 + ty * 8];
            float4 p1 = *(float4*)&PsT[j * 132 + ty * 8 + 4];
            float4 v0 = *(float4*)&Vs[j * 68 + tx * 4];
            float pr[8] = {p0.x, p0.y, p0.z, p0.w, p1.x, p1.y, p1.z, p1.w};
            float vr[4] = {v0.x, v0.y, v0.z, v0.w};
#pragma unroll
            for (int i = 0; i < 8; i++)
#pragma unroll
                for (int c = 0; c < 4; c++)
                    acc[i][c] = fmaf(pr[i], vr[c], acc[i][c]);
        }
    }

    // Epilogue: normalize and store directly into [B, N, DIM] layout
#pragma unroll
    for (int i = 0; i < 8; i++) {
        float inv = 1.f / l_run[i];
        float4 o = make_float4(acc[i][0] * inv, acc[i][1] * inv,
                               acc[i][2] * inv, acc[i][3] * inv);
        *(float4*)(wa + (size_t)(b * NN + qt * 128 + ty * 8 + i) * DIM
                      + h * HD + tx * 4) = o;
    }
}

// ---------------------------------------------------------------------------
extern "C" void kernel_launch(void* const* d_in, const int* in_sizes, int n_in,
                              void* d_out, int out_size)
{
    (void)in_sizes; (void)n_in; (void)out_size;
    const float* en    = (const float*)d_in[0];
    const float* dec   = (const float*)d_in[1];
    const float* Wkv   = (const float*)d_in[2];
    const float* bkv   = (const float*)d_in[3];
    const float* Wproj = (const float*)d_in[4];
    const float* bproj = (const float*)d_in[5];
    float* out = (float*)d_out;

    float *kvp, *wap;
    cudaGetSymbolAddress((void**)&kvp, g_kv);
    cudaGetSymbolAddress((void**)&wap, g_wa);

    cudaFuncSetAttribute(attn_kernel,
                         cudaFuncAttributeMaxDynamicSharedMemorySize,
                         ATTN_SMEM_BYTES);

    // 1) kv = en @ Wkv + bkv        [8192 x 1536]
    gemm_bias_kernel<<<dim3(KV_N / 128, M_TOTAL / 128), 256>>>(
        en, Wkv, bkv, kvp, M_TOTAL, KV_N, DIM);

    // 2) attention -> wa            [8192 x 768]
    attn_kernel<<<dim3(NN / 128, NH, BB), 256, ATTN_SMEM_BYTES>>>(dec, kvp, wap);

    // 3) out = wa @ Wproj + bproj   [8192 x 768]
    gemm_bias_kernel<<<dim3(DIM / 128, M_TOTAL / 128), 256>>>(
        wap, Wproj, bproj, out, M_TOTAL, DIM, DIM);
}

// round 3
// speedup vs baseline: 1.2539x; 1.2539x over previous
#include <cuda_runtime.h>
#include <cuda_bf16.h>
#include <math.h>
#include <stdint.h>

// Problem constants
#define BB   8
#define NN   1024
#define DIM  768
#define NH   12
#define HD   64
#define SCALE 0.125f   // HD^-0.5

#define M_TOTAL (BB*NN)          // 8192
#define KV_N    (2*DIM)          // 1536

// ---------------------------------------------------------------------------
// Scratch (device globals: allocation-free per harness rules)
// ---------------------------------------------------------------------------
__device__ __align__(256) float g_kv[M_TOTAL * KV_N];   // [B*N, 1536] fp32

__device__ __align__(256) __nv_bfloat16 g_enhi[M_TOTAL * DIM];
__device__ __align__(256) __nv_bfloat16 g_enlo[M_TOTAL * DIM];
__device__ __align__(256) __nv_bfloat16 g_wahi[M_TOTAL * DIM];
__device__ __align__(256) __nv_bfloat16 g_walo[M_TOTAL * DIM];
__device__ __align__(256) __nv_bfloat16 g_Wkvthi[KV_N * DIM];   // [1536][768] (N,K)
__device__ __align__(256) __nv_bfloat16 g_Wkvtlo[KV_N * DIM];
__device__ __align__(256) __nv_bfloat16 g_Wpthi[DIM * DIM];     // [768][768]  (N,K)
__device__ __align__(256) __nv_bfloat16 g_Wptlo[DIM * DIM];

// ---------------------------------------------------------------------------
// Low-level helpers (baseline sm_100 PTX: mma.sync + ldmatrix + cp.async)
// ---------------------------------------------------------------------------
__device__ __forceinline__ uint32_t smem_to_u32(const void* smem_ptr) {
    uint32_t addr;
    asm("{ .reg .u64 tmp; cvta.to.shared.u64 tmp, %1; cvt.u32.u64 %0, tmp; }"
        : "=r"(addr) : "l"(smem_ptr));
    return addr;
}

#define CP_ASYNC_16(dst_u32, src_ptr) \
    asm volatile("cp.async.cg.shared.global [%0], [%1], 16;" \
                 :: "r"(dst_u32), "l"(src_ptr))
#define CP_COMMIT() asm volatile("cp.async.commit_group;" ::: "memory")
#define CP_WAIT0()  asm volatile("cp.async.wait_group 0;" ::: "memory")
#define CP_WAIT1()  asm volatile("cp.async.wait_group 1;" ::: "memory")

__device__ __forceinline__ void ldm_x4(uint32_t addr, uint32_t& r0, uint32_t& r1,
                                       uint32_t& r2, uint32_t& r3) {
    asm volatile("ldmatrix.sync.aligned.m8n8.x4.shared.b16 {%0,%1,%2,%3}, [%4];"
                 : "=r"(r0), "=r"(r1), "=r"(r2), "=r"(r3) : "r"(addr));
}

__device__ __forceinline__ void mma_bf16(float& c0, float& c1, float& c2, float& c3,
                                         uint32_t a0, uint32_t a1, uint32_t a2,
                                         uint32_t a3, uint32_t b0, uint32_t b1) {
    asm volatile(
        "mma.sync.aligned.m16n8k16.row.col.f32.bf16.bf16.f32 "
        "{%0,%1,%2,%3}, {%4,%5,%6,%7}, {%8,%9}, {%0,%1,%2,%3};"
        : "+f"(c0), "+f"(c1), "+f"(c2), "+f"(c3)
        : "r"(a0), "r"(a1), "r"(a2), "r"(a3), "r"(b0), "r"(b1));
}

// ---------------------------------------------------------------------------
// Tensor-core GEMM with bf16 hi/lo split (3 MMA terms, lo*lo dropped):
//   C[M,N] = (Ahi+Alo)[M,K] @ (Bhi+Blo)^T + bias,   B given as Bt[N,K]
// CTA tile 128x128, BK=32, 8 warps (4m x 2n), warp tile 32x64.
// Smem tile rows: 32 bf16 = 64 data bytes padded to 80 bytes; k-chunk
// (16B) swizzle: phys_chunk = chunk ^ (row & 3)  -> conflict-free for both
// cp.async stores and ldmatrix loads.
// Stage = 4 tensors * 128 rows * 80B = 40960 B; 2 stages = 81920 B.
// ---------------------------------------------------------------------------
#define GT_SMEM_BYTES 81920
#define TILE_STRIDE   80
#define TENSOR_BYTES  (128 * TILE_STRIDE)   // 10240
#define STAGE_BYTES   (4 * TENSOR_BYTES)    // 40960

__device__ __forceinline__ uint32_t tile_addr(uint32_t base, int r, int kb16) {
    return base + r * TILE_STRIDE + ((kb16 ^ (r & 3)) << 4);
}

__global__ __launch_bounds__(256)
void gemm_tc_kernel(const __nv_bfloat16* __restrict__ Ahi,
                    const __nv_bfloat16* __restrict__ Alo,
                    const __nv_bfloat16* __restrict__ Bhi,
                    const __nv_bfloat16* __restrict__ Blo,
                    const float* __restrict__ bias,
                    float* __restrict__ C, int M, int N, int K)
{
    extern __shared__ __align__(128) char smem[];
    const uint32_t smem_base = smem_to_u32(smem);

    const int tid  = threadIdx.x;
    const int wid  = tid >> 5;
    const int lane = tid & 31;
    const int wm   = wid & 3;          // warp m index (32 rows)
    const int wn   = wid >> 2;         // warp n index (64 cols)
    const int m0   = blockIdx.y * 128;
    const int n0   = blockIdx.x * 128;

    const __nv_bfloat16* srcs[4] = {
        Ahi + (size_t)m0 * K, Alo + (size_t)m0 * K,
        Bhi + (size_t)n0 * K, Blo + (size_t)n0 * K };

    // per-thread load slots: idx = i*256+tid; t=idx>>9, j=idx&511, r=j>>2, c=j&3
    auto load_chunk = [&](int chunk, int s) {
        const int k0 = chunk * 32;
        const uint32_t sbase = smem_base + s * STAGE_BYTES;
#pragma unroll
        for (int i = 0; i < 8; i++) {
            int idx = i * 256 + tid;
            int t = idx >> 9;
            int j = idx & 511;
            int r = j >> 2;
            int c = j & 3;
            const __nv_bfloat16* src = srcs[t] + (size_t)r * K + k0 + c * 8;
            CP_ASYNC_16(tile_addr(sbase + t * TENSOR_BYTES, r, c), src);
        }
    };

    float acc[2][8][4];
#pragma unroll
    for (int mf = 0; mf < 2; mf++)
#pragma unroll
        for (int nf = 0; nf < 8; nf++)
#pragma unroll
            for (int e = 0; e < 4; e++) acc[mf][nf][e] = 0.f;

    // ldmatrix lane geometry (same for A and B tiles)
    const int i8   = lane & 7;
    const int quad = lane >> 3;
    const int qr   = (quad & 1) << 3;   // +8 rows for quads 1,3
    const int qc   = quad >> 1;         // +1 k-chunk for quads 2,3

    const int NCHUNK = K >> 5;          // K/32

    load_chunk(0, 0);
    CP_COMMIT();

    for (int ch = 0; ch < NCHUNK; ch++) {
        const int s = ch & 1;
        if (ch + 1 < NCHUNK) {
            load_chunk(ch + 1, s ^ 1);
            CP_COMMIT();
            CP_WAIT1();
        } else {
            CP_WAIT0();
        }
        __syncthreads();

        const uint32_t sbase = smem_base + s * STAGE_BYTES;
        const uint32_t aHiB = sbase;
        const uint32_t aLoB = sbase + TENSOR_BYTES;
        const uint32_t bHiB = sbase + 2 * TENSOR_BYTES;
        const uint32_t bLoB = sbase + 3 * TENSOR_BYTES;

#pragma unroll
        for (int kf = 0; kf < 2; kf++) {
            const int kb = kf * 2 + qc;

            uint32_t ah[2][4], al[2][4];
#pragma unroll
            for (int mf = 0; mf < 2; mf++) {
                int r = wm * 32 + mf * 16 + i8 + qr;
                ldm_x4(tile_addr(aHiB, r, kb), ah[mf][0], ah[mf][1], ah[mf][2], ah[mf][3]);
                ldm_x4(tile_addr(aLoB, r, kb), al[mf][0], al[mf][1], al[mf][2], al[mf][3]);
            }
            uint32_t bh[4][4], bl[4][4];
#pragma unroll
            for (int nf2 = 0; nf2 < 4; nf2++) {
                int r = wn * 64 + nf2 * 16 + i8 + qr;
                ldm_x4(tile_addr(bHiB, r, kb), bh[nf2][0], bh[nf2][1], bh[nf2][2], bh[nf2][3]);
                ldm_x4(tile_addr(bLoB, r, kb), bl[nf2][0], bl[nf2][1], bl[nf2][2], bl[nf2][3]);
            }
#pragma unroll
            for (int mf = 0; mf < 2; mf++)
#pragma unroll
                for (int nf = 0; nf < 8; nf++) {
                    const int nf2 = nf >> 1, od = nf & 1;
                    float* c = acc[mf][nf];
                    mma_bf16(c[0], c[1], c[2], c[3],
                             ah[mf][0], ah[mf][1], ah[mf][2], ah[mf][3],
                             bh[nf2][od], bh[nf2][od + 2]);
                    mma_bf16(c[0], c[1], c[2], c[3],
                             ah[mf][0], ah[mf][1], ah[mf][2], ah[mf][3],
                             bl[nf2][od], bl[nf2][od + 2]);
                    mma_bf16(c[0], c[1], c[2], c[3],
                             al[mf][0], al[mf][1], al[mf][2], al[mf][3],
                             bh[nf2][od], bh[nf2][od + 2]);
                }
        }
        __syncthreads();
    }

    // Epilogue: add bias, store. Thread (mf,nf) owns rows {r0, r0+8}, cols col..col+1
#pragma unroll
    for (int mf = 0; mf < 2; mf++) {
        const int r0 = m0 + wm * 32 + mf * 16 + (lane >> 2);
#pragma unroll
        for (int nf = 0; nf < 8; nf++) {
            const int col = n0 + wn * 64 + nf * 8 + (lane & 3) * 2;
            float2 bv = *(const float2*)(bias + col);
            float2 v0 = make_float2(acc[mf][nf][0] + bv.x, acc[mf][nf][1] + bv.y);
            float2 v1 = make_float2(acc[mf][nf][2] + bv.x, acc[mf][nf][3] + bv.y);
            *(float2*)(C + (size_t)r0 * N + col) = v0;
            *(float2*)(C + (size_t)(r0 + 8) * N + col) = v1;
        }
    }
}

// ---------------------------------------------------------------------------
// fp32 -> bf16 hi/lo split (elementwise, vectorized by 4)
// ---------------------------------------------------------------------------
__global__ __launch_bounds__(256)
void split_kernel(const float4* __restrict__ x, uint2* __restrict__ hi,
                  uint2* __restrict__ lo, int n4)
{
    int i = blockIdx.x * blockDim.x + threadIdx.x;
    if (i >= n4) return;
    float4 v = x[i];
    __nv_bfloat16 h[4], l[4];
    float f[4] = {v.x, v.y, v.z, v.w};
#pragma unroll
    for (int j = 0; j < 4; j++) {
        h[j] = __float2bfloat16(f[j]);
        l[j] = __float2bfloat16(f[j] - __bfloat162float(h[j]));
    }
    uint2 hp, lp;
    hp.x = ((uint32_t)*(uint16_t*)&h[1] << 16) | *(uint16_t*)&h[0];
    hp.y = ((uint32_t)*(uint16_t*)&h[3] << 16) | *(uint16_t*)&h[2];
    lp.x = ((uint32_t)*(uint16_t*)&l[1] << 16) | *(uint16_t*)&l[0];
    lp.y = ((uint32_t)*(uint16_t*)&l[3] << 16) | *(uint16_t*)&l[2];
    hi[i] = hp;
    lo[i] = lp;
}

// ---------------------------------------------------------------------------
// Weight transpose + split: W[K,N] fp32 -> Wt_hi/lo[N,K] bf16
// ---------------------------------------------------------------------------
__global__ __launch_bounds__(256)
void tsplit_kernel(const float* __restrict__ W, __nv_bfloat16* __restrict__ thi,
                   __nv_bfloat16* __restrict__ tlo, int K, int N)
{
    __shared__ float t[32][33];
    const int n0 = blockIdx.x * 32, k0 = blockIdx.y * 32;
    const int tx = threadIdx.x, ty = threadIdx.y;   // 32 x 8
#pragma unroll
    for (int i = 0; i < 4; i++)
        t[ty + 8 * i][tx] = W[(size_t)(k0 + ty + 8 * i) * N + n0 + tx];
    __syncthreads();
#pragma unroll
    for (int i = 0; i < 4; i++) {
        int r = ty + 8 * i;
        float v = t[tx][r];                 // = W[k0+tx][n0+r]
        __nv_bfloat16 h = __float2bfloat16(v);
        size_t o = (size_t)(n0 + r) * K + k0 + tx;
        thi[o] = h;
        tlo[o] = __float2bfloat16(v - __bfloat162float(h));
    }
}

// ---------------------------------------------------------------------------
// Fused attention (fp32): per block one (b, h, 128-query tile).
// Epilogue writes wa directly as bf16 hi/lo (feeds the projection GEMM).
// ---------------------------------------------------------------------------
#define ATTN_SMEM_BYTES 102400

__global__ __launch_bounds__(256)
void attn_kernel(const float* __restrict__ dec, const float* __restrict__ kv,
                 __nv_bfloat16* __restrict__ wahi, __nv_bfloat16* __restrict__ walo)
{
    extern __shared__ float sm[];
    float* QsT = sm;                       // [64][132]
    float* KsT = QsT + 64 * 132;           // [64][68]
    float* Vs  = KsT + 64 * 68;            // [64][68]
    float* PsT = Vs  + 64 * 68;            // [64][132]

    const int b  = blockIdx.z;
    const int h  = blockIdx.y;
    const int qt = blockIdx.x;
    const int tid = threadIdx.x;
    const int ty = tid >> 4;
    const int tx = tid & 15;

    {
        const float* qbase = dec + (size_t)(b * NN + qt * 128) * DIM + h * HD;
#pragma unroll
        for (int i = 0; i < 8; i++) {
            int idx = tid + i * 256;
            int r  = idx >> 4;
            int dq = idx & 15;
            float4 q4 = *(const float4*)(qbase + (size_t)r * DIM + dq * 4);
            QsT[(dq*4+0) * 132 + r] = q4.x;
            QsT[(dq*4+1) * 132 + r] = q4.y;
            QsT[(dq*4+2) * 132 + r] = q4.z;
            QsT[(dq*4+3) * 132 + r] = q4.w;
        }
    }

    float acc[8][4];
    float m_run[8], l_run[8];
#pragma unroll
    for (int i = 0; i < 8; i++) {
        m_run[i] = -1e30f;
        l_run[i] = 0.f;
#pragma unroll
        for (int c = 0; c < 4; c++) acc[i][c] = 0.f;
    }

    const float* kbase = kv + (size_t)b * NN * KV_N + h * HD;
    const float* vbase = kbase + DIM;

    for (int kt = 0; kt < NN / 64; kt++) {
        __syncthreads();

#pragma unroll
        for (int i = 0; i < 4; i++) {
            int idx = tid + i * 256;
            int j  = idx >> 4;
            int dq = idx & 15;
            const float* kp = kbase + (size_t)(kt * 64 + j) * KV_N + dq * 4;
            float4 k4 = *(const float4*)kp;
            KsT[(dq*4+0) * 68 + j] = k4.x;
            KsT[(dq*4+1) * 68 + j] = k4.y;
            KsT[(dq*4+2) * 68 + j] = k4.z;
            KsT[(dq*4+3) * 68 + j] = k4.w;
            float4 v4 = *(const float4*)(vbase + (size_t)(kt * 64 + j) * KV_N + dq * 4);
            *(float4*)&Vs[j * 68 + dq * 4] = v4;
        }
        __syncthreads();

        float s[8][4];
#pragma unroll
        for (int i = 0; i < 8; i++)
#pragma unroll
            for (int c = 0; c < 4; c++) s[i][c] = 0.f;

#pragma unroll 8
        for (int d = 0; d < 64; d++) {
            float4 a0 = *(float4*)&QsT[d * 132 + ty * 8];
            float4 a1 = *(float4*)&QsT[d * 132 + ty * 8 + 4];
            float4 b0 = *(float4*)&KsT[d * 68 + tx * 4];
            float ar[8] = {a0.x, a0.y, a0.z, a0.w, a1.x, a1.y, a1.z, a1.w};
            float br[4] = {b0.x, b0.y, b0.z, b0.w};
#pragma unroll
            for (int i = 0; i < 8; i++)
#pragma unroll
                for (int c = 0; c < 4; c++)
                    s[i][c] = fmaf(ar[i], br[c], s[i][c]);
        }

#pragma unroll
        for (int i = 0; i < 8; i++) {
#pragma unroll
            for (int c = 0; c < 4; c++) s[i][c] *= SCALE;
            float mx = fmaxf(fmaxf(s[i][0], s[i][1]), fmaxf(s[i][2], s[i][3]));
#pragma unroll
            for (int off = 8; off >= 1; off >>= 1)
                mx = fmaxf(mx, __shfl_xor_sync(0xffffffffu, mx, off));
            float newm = fmaxf(m_run[i], mx);
            float alpha = __expf(m_run[i] - newm);
            m_run[i] = newm;
            float rsum = 0.f;
#pragma unroll
            for (int c = 0; c < 4; c++) {
                float p = __expf(s[i][c] - newm);
                rsum += p;
                PsT[(tx * 4 + c) * 132 + ty * 8 + i] = p;
            }
#pragma unroll
            for (int off = 8; off >= 1; off >>= 1)
                rsum += __shfl_xor_sync(0xffffffffu, rsum, off);
            l_run[i] = l_run[i] * alpha + rsum;
#pragma unroll
            for (int c = 0; c < 4; c++) acc[i][c] *= alpha;
        }
        __syncthreads();

#pragma unroll 8
        for (int j = 0; j < 64; j++) {
            float4 p0 = *(float4*)&PsT[j * 132 + ty * 8];
            float4 p1 = *(float4*)&PsT[j * 132 + ty * 8 + 4];
            float4 v0 = *(float4*)&Vs[j * 68 + tx * 4];
            float pr[8] = {p0.x, p0.y, p0.z, p0.w, p1.x, p1.y, p1.z, p1.w};
            float vr[4] = {v0.x, v0.y, v0.z, v0.w};
#pragma unroll
            for (int i = 0; i < 8; i++)
#pragma unroll
                for (int c = 0; c < 4; c++)
                    acc[i][c] = fmaf(pr[i], vr[c], acc[i][c]);
        }
    }

    // Epilogue: normalize, split to bf16 hi/lo, store in [B, N, DIM] layout
#pragma unroll
    for (int i = 0; i < 8; i++) {
        float inv = 1.f / l_run[i];
        float o[4];
        __nv_bfloat16 h4[4], l4[4];
#pragma unroll
        for (int c = 0; c < 4; c++) {
            o[c] = acc[i][c] * inv;
            h4[c] = __float2bfloat16(o[c]);
            l4[c] = __float2bfloat16(o[c] - __bfloat162float(h4[c]));
        }
        uint2 hp, lp;
        hp.x = ((uint32_t)*(uint16_t*)&h4[1] << 16) | *(uint16_t*)&h4[0];
        hp.y = ((uint32_t)*(uint16_t*)&h4[3] << 16) | *(uint16_t*)&h4[2];
        lp.x = ((uint32_t)*(uint16_t*)&l4[1] << 16) | *(uint16_t*)&l4[0];
        lp.y = ((uint32_t)*(uint16_t*)&l4[3] << 16) | *(uint16_t*)&l4[2];
        size_t off = (size_t)(b * NN + qt * 128 + ty * 8 + i) * DIM + h * HD + tx * 4;
        *(uint2*)(wahi + off) = hp;
        *(uint2*)(walo + off) = lp;
    }
}

// ---------------------------------------------------------------------------
extern "C" void kernel_launch(void* const* d_in, const int* in_sizes, int n_in,
                              void* d_out, int out_size)
{
    (void)in_sizes; (void)n_in; (void)out_size;
    const float* en    = (const float*)d_in[0];
    const float* dec   = (const float*)d_in[1];
    const float* Wkv   = (const float*)d_in[2];
    const float* bkv   = (const float*)d_in[3];
    const float* Wproj = (const float*)d_in[4];
    const float* bproj = (const float*)d_in[5];
    float* out = (float*)d_out;

    float* kvp;
    __nv_bfloat16 *enhi, *enlo, *wahi, *walo, *wkvthi, *wkvtlo, *wpthi, *wptlo;
    cudaGetSymbolAddress((void**)&kvp, g_kv);
    cudaGetSymbolAddress((void**)&enhi, g_enhi);
    cudaGetSymbolAddress((void**)&enlo, g_enlo);
    cudaGetSymbolAddress((void**)&wahi, g_wahi);
    cudaGetSymbolAddress((void**)&walo, g_walo);
    cudaGetSymbolAddress((void**)&wkvthi, g_Wkvthi);
    cudaGetSymbolAddress((void**)&wkvtlo, g_Wkvtlo);
    cudaGetSymbolAddress((void**)&wpthi, g_Wpthi);
    cudaGetSymbolAddress((void**)&wptlo, g_Wptlo);

    cudaFuncSetAttribute(attn_kernel,
                         cudaFuncAttributeMaxDynamicSharedMemorySize,
                         ATTN_SMEM_BYTES);
    cudaFuncSetAttribute(gemm_tc_kernel,
                         cudaFuncAttributeMaxDynamicSharedMemorySize,
                         GT_SMEM_BYTES);

    // 0) split inputs / weights to bf16 hi/lo
    {
        int n4 = M_TOTAL * DIM / 4;
        split_kernel<<<n4 / 256, 256>>>((const float4*)en, (uint2*)enhi,
                                        (uint2*)enlo, n4);
    }
    tsplit_kernel<<<dim3(KV_N / 32, DIM / 32), dim3(32, 8)>>>(
        Wkv, wkvthi, wkvtlo, DIM, KV_N);
    tsplit_kernel<<<dim3(DIM / 32, DIM / 32), dim3(32, 8)>>>(
        Wproj, wpthi, wptlo, DIM, DIM);

    // 1) kv = en @ Wkv + bkv   [8192 x 1536]  (tensor cores, mma.sync)
    gemm_tc_kernel<<<dim3(KV_N / 128, M_TOTAL / 128), 256, GT_SMEM_BYTES>>>(
        enhi, enlo, wkvthi, wkvtlo, bkv, kvp, M_TOTAL, KV_N, DIM);

    // 2) attention -> wa (bf16 hi/lo)   [8192 x 768]
    attn_kernel<<<dim3(NN / 128, NH, BB), 256, ATTN_SMEM_BYTES>>>(
        dec, kvp, wahi, walo);

    // 3) out = wa @ Wproj + bproj  (tensor cores, mma.sync)
    gemm_tc_kernel<<<dim3(DIM / 128, M_TOTAL / 128), 256, GT_SMEM_BYTES>>>(
        wahi, walo, wpthi, wptlo, bproj, out, M_TOTAL, DIM, DIM);
}

// round 4
// speedup vs baseline: 2.3453x; 1.8705x over previous
#include <cuda_runtime.h>
#include <cuda_bf16.h>
#include <cuda_fp16.h>
#include <math.h>
#include <stdint.h>

// Problem constants
#define BB   8
#define NN   1024
#define DIM  768
#define NH   12
#define HD   64

#define M_TOTAL (BB*NN)          // 8192
#define KV_N    (2*DIM)          // 1536

// 0.125 * log2(e): folded into Q so exp(s*0.125) = 2^(S_acc)
#define QSCALE 0.180336880596349f

// ---------------------------------------------------------------------------
// Scratch (device globals)
// ---------------------------------------------------------------------------
__device__ __align__(256) __nv_bfloat16 g_enhi[M_TOTAL * DIM];
__device__ __align__(256) __nv_bfloat16 g_enlo[M_TOTAL * DIM];
__device__ __align__(256) __nv_bfloat16 g_wahi[M_TOTAL * DIM];
__device__ __align__(256) __nv_bfloat16 g_walo[M_TOTAL * DIM];
__device__ __align__(256) __nv_bfloat16 g_Wkvthi[KV_N * DIM];   // [1536][768] (N,K)
__device__ __align__(256) __nv_bfloat16 g_Wkvtlo[KV_N * DIM];
__device__ __align__(256) __nv_bfloat16 g_Wpthi[DIM * DIM];     // [768][768]  (N,K)
__device__ __align__(256) __nv_bfloat16 g_Wptlo[DIM * DIM];

// K: [8192][768] fp16 hi/lo (seq-major, head-d contiguous)
__device__ __align__(256) __half g_khi[M_TOTAL * DIM];
__device__ __align__(256) __half g_klo[M_TOTAL * DIM];
// V transposed: [B][768 d][1024 seq] fp16 hi/lo
__device__ __align__(256) __half g_vhiT[BB * DIM * NN];
__device__ __align__(256) __half g_vloT[BB * DIM * NN];

// ---------------------------------------------------------------------------
// Low-level helpers
// ---------------------------------------------------------------------------
__device__ __forceinline__ uint32_t smem_to_u32(const void* smem_ptr) {
    uint32_t addr;
    asm("{ .reg .u64 tmp; cvta.to.shared.u64 tmp, %1; cvt.u32.u64 %0, tmp; }"
        : "=r"(addr) : "l"(smem_ptr));
    return addr;
}

#define CP_ASYNC_16(dst_u32, src_ptr) \
    asm volatile("cp.async.cg.shared.global [%0], [%1], 16;" \
                 :: "r"(dst_u32), "l"(src_ptr))
#define CP_COMMIT() asm volatile("cp.async.commit_group;" ::: "memory")
#define CP_WAIT0()  asm volatile("cp.async.wait_group 0;" ::: "memory")
#define CP_WAIT1()  asm volatile("cp.async.wait_group 1;" ::: "memory")

__device__ __forceinline__ void ldm_x4(uint32_t addr, uint32_t& r0, uint32_t& r1,
                                       uint32_t& r2, uint32_t& r3) {
    asm volatile("ldmatrix.sync.aligned.m8n8.x4.shared.b16 {%0,%1,%2,%3}, [%4];"
                 : "=r"(r0), "=r"(r1), "=r"(r2), "=r"(r3) : "r"(addr));
}

__device__ __forceinline__ void mma_bf16(float* c, uint32_t a0, uint32_t a1,
                                         uint32_t a2, uint32_t a3,
                                         uint32_t b0, uint32_t b1) {
    asm volatile(
        "mma.sync.aligned.m16n8k16.row.col.f32.bf16.bf16.f32 "
        "{%0,%1,%2,%3}, {%4,%5,%6,%7}, {%8,%9}, {%0,%1,%2,%3};"
        : "+f"(c[0]), "+f"(c[1]), "+f"(c[2]), "+f"(c[3])
        : "r"(a0), "r"(a1), "r"(a2), "r"(a3), "r"(b0), "r"(b1));
}

__device__ __forceinline__ void mma_f16(float* c, uint32_t a0, uint32_t a1,
                                        uint32_t a2, uint32_t a3,
                                        uint32_t b0, uint32_t b1) {
    asm volatile(
        "mma.sync.aligned.m16n8k16.row.col.f32.f16.f16.f32 "
        "{%0,%1,%2,%3}, {%4,%5,%6,%7}, {%8,%9}, {%0,%1,%2,%3};"
        : "+f"(c[0]), "+f"(c[1]), "+f"(c[2]), "+f"(c[3])
        : "r"(a0), "r"(a1), "r"(a2), "r"(a3), "r"(b0), "r"(b1));
}

__device__ __forceinline__ float ex2f(float x) {
    float y;
    asm("ex2.approx.f32 %0, %1;" : "=f"(y) : "f"(x));
    return y;
}

__device__ __forceinline__ uint32_t packh2(float lo, float hi) {
    half2 h = __floats2half2_rn(lo, hi);
    return *reinterpret_cast<uint32_t*>(&h);
}

// ---------------------------------------------------------------------------
// GEMM tile machinery shared by both GEMMs (bf16 hi/lo, 3 terms, BK=32)
// ---------------------------------------------------------------------------
#define GT_SMEM_BYTES 81920
#define TILE_STRIDE   80
#define TENSOR_BYTES  (128 * TILE_STRIDE)   // 10240
#define STAGE_BYTES   (4 * TENSOR_BYTES)    // 40960

__device__ __forceinline__ uint32_t tile_addr(uint32_t base, int r, int kb16) {
    return base + r * TILE_STRIDE + ((kb16 ^ (r & 3)) << 4);
}

// Mainloop: computes acc[2][8][4] for a 128x128 tile (macro-style inline fn)
template <typename EpilogueFn>
__device__ __forceinline__ void gemm_tile(
    const __nv_bfloat16* Ahi, const __nv_bfloat16* Alo,
    const __nv_bfloat16* Bhi, const __nv_bfloat16* Blo,
    int K, int m0, int n0, uint32_t smem_base, EpilogueFn epi)
{
    const int tid  = threadIdx.x;
    const int lane = tid & 31;

    const __nv_bfloat16* srcs[4] = {
        Ahi + (size_t)m0 * K, Alo + (size_t)m0 * K,
        Bhi + (size_t)n0 * K, Blo + (size_t)n0 * K };

    auto load_chunk = [&](int chunk, int s) {
        const int k0 = chunk * 32;
        const uint32_t sbase = smem_base + s * STAGE_BYTES;
#pragma unroll
        for (int i = 0; i < 8; i++) {
            int t = i >> 1;
            int j = (i & 1) * 256 + tid;
            int r = j >> 2;
            int c = j & 3;
            const __nv_bfloat16* src = srcs[t] + (size_t)r * K + k0 + c * 8;
            CP_ASYNC_16(tile_addr(sbase + t * TENSOR_BYTES, r, c), src);
        }
    };

    float acc[2][8][4];
#pragma unroll
    for (int mf = 0; mf < 2; mf++)
#pragma unroll
        for (int nf = 0; nf < 8; nf++)
#pragma unroll
            for (int e = 0; e < 4; e++) acc[mf][nf][e] = 0.f;

    const int wid = tid >> 5;
    const int wm  = wid & 3;
    const int wn  = wid >> 2;
    const int i8   = lane & 7;
    const int quad = lane >> 3;
    const int qr   = (quad & 1) << 3;
    const int qc   = quad >> 1;

    const int NCHUNK = K >> 5;

    load_chunk(0, 0);
    CP_COMMIT();

    for (int ch = 0; ch < NCHUNK; ch++) {
        const int s = ch & 1;
        if (ch + 1 < NCHUNK) {
            load_chunk(ch + 1, s ^ 1);
            CP_COMMIT();
            CP_WAIT1();
        } else {
            CP_WAIT0();
        }
        __syncthreads();

        const uint32_t sbase = smem_base + s * STAGE_BYTES;
        const uint32_t aHiB = sbase;
        const uint32_t aLoB = sbase + TENSOR_BYTES;
        const uint32_t bHiB = sbase + 2 * TENSOR_BYTES;
        const uint32_t bLoB = sbase + 3 * TENSOR_BYTES;

#pragma unroll
        for (int kf = 0; kf < 2; kf++) {
            const int kb = kf * 2 + qc;
            uint32_t ah[2][4], al[2][4];
#pragma unroll
            for (int mf = 0; mf < 2; mf++) {
                int r = wm * 32 + mf * 16 + i8 + qr;
                ldm_x4(tile_addr(aHiB, r, kb), ah[mf][0], ah[mf][1], ah[mf][2], ah[mf][3]);
                ldm_x4(tile_addr(aLoB, r, kb), al[mf][0], al[mf][1], al[mf][2], al[mf][3]);
            }
            uint32_t bh[4][4], bl[4][4];
#pragma unroll
            for (int nf2 = 0; nf2 < 4; nf2++) {
                int r = wn * 64 + nf2 * 16 + i8 + qr;
                ldm_x4(tile_addr(bHiB, r, kb), bh[nf2][0], bh[nf2][1], bh[nf2][2], bh[nf2][3]);
                ldm_x4(tile_addr(bLoB, r, kb), bl[nf2][0], bl[nf2][1], bl[nf2][2], bl[nf2][3]);
            }
#pragma unroll
            for (int mf = 0; mf < 2; mf++)
#pragma unroll
                for (int nf = 0; nf < 8; nf++) {
                    const int nf2 = nf >> 1, od = nf & 1;
                    float* c = acc[mf][nf];
                    mma_bf16(c, ah[mf][0], ah[mf][1], ah[mf][2], ah[mf][3],
                             bh[nf2][od], bh[nf2][od + 2]);
                    mma_bf16(c, ah[mf][0], ah[mf][1], ah[mf][2], ah[mf][3],
                             bl[nf2][od], bl[nf2][od + 2]);
                    mma_bf16(c, al[mf][0], al[mf][1], al[mf][2], al[mf][3],
                             bh[nf2][od], bh[nf2][od + 2]);
                }
        }
        __syncthreads();
    }
    epi(acc, wm, wn, lane);
}

// GEMM1: kv projection, epilogue writes K (fp16 hi/lo) and V (transposed fp16 hi/lo)
__global__ __launch_bounds__(256, 2)
void gemm_kv_kernel(const __nv_bfloat16* __restrict__ Ahi,
                    const __nv_bfloat16* __restrict__ Alo,
                    const __nv_bfloat16* __restrict__ Bhi,
                    const __nv_bfloat16* __restrict__ Blo,
                    const float* __restrict__ bias,
                    __half* __restrict__ khi, __half* __restrict__ klo,
                    __half* __restrict__ vhiT, __half* __restrict__ vloT)
{
    extern __shared__ __align__(128) char smem[];
    const uint32_t smem_base = smem_to_u32(smem);
    const int m0 = blockIdx.y * 128;
    const int n0 = blockIdx.x * 128;
    const bool isV = (n0 >= DIM);

    gemm_tile(Ahi, Alo, Bhi, Blo, DIM, m0, n0, smem_base,
        [&](float acc[2][8][4], int wm, int wn, int lane) {
#pragma unroll
            for (int mf = 0; mf < 2; mf++) {
                const int r0 = m0 + wm * 32 + mf * 16 + (lane >> 2);
#pragma unroll
                for (int nf = 0; nf < 8; nf++) {
                    const int col = n0 + wn * 64 + nf * 8 + (lane & 3) * 2;
                    float2 bv = *(const float2*)(bias + col);
                    float c0 = acc[mf][nf][0] + bv.x;
                    float c1 = acc[mf][nf][1] + bv.y;
                    float c2 = acc[mf][nf][2] + bv.x;
                    float c3 = acc[mf][nf][3] + bv.y;
                    __half h0 = __float2half_rn(c0), h1 = __float2half_rn(c1);
                    __half h2 = __float2half_rn(c2), h3 = __float2half_rn(c3);
                    __half l0 = __float2half_rn(c0 - __half2float(h0));
                    __half l1 = __float2half_rn(c1 - __half2float(h1));
                    __half l2 = __float2half_rn(c2 - __half2float(h2));
                    __half l3 = __float2half_rn(c3 - __half2float(h3));
                    if (!isV) {
                        uint32_t hp0 = ((uint32_t)*(uint16_t*)&h1 << 16) | *(uint16_t*)&h0;
                        uint32_t hp1 = ((uint32_t)*(uint16_t*)&h3 << 16) | *(uint16_t*)&h2;
                        uint32_t lp0 = ((uint32_t)*(uint16_t*)&l1 << 16) | *(uint16_t*)&l0;
                        uint32_t lp1 = ((uint32_t)*(uint16_t*)&l3 << 16) | *(uint16_t*)&l2;
                        *(uint32_t*)(khi + (size_t)r0 * DIM + col) = hp0;
                        *(uint32_t*)(khi + (size_t)(r0 + 8) * DIM + col) = hp1;
                        *(uint32_t*)(klo + (size_t)r0 * DIM + col) = lp0;
                        *(uint32_t*)(klo + (size_t)(r0 + 8) * DIM + col) = lp1;
                    } else {
                        const int d = col - DIM;
                        const int b = r0 >> 10, seq = r0 & 1023;
                        size_t o00 = ((size_t)(b * DIM + d)) * NN + seq;
                        size_t o10 = o00 + NN;          // d+1
                        vhiT[o00] = h0;      vhiT[o10] = h1;
                        vhiT[o00 + 8] = h2;  vhiT[o10 + 8] = h3;   // seq+8
                        vloT[o00] = l0;      vloT[o10] = l1;
                        vloT[o00 + 8] = l2;  vloT[o10 + 8] = l3;
                    }
                }
            }
        });
}

// GEMM2: output projection, fp32 out + bias
__global__ __launch_bounds__(256, 2)
void gemm_out_kernel(const __nv_bfloat16* __restrict__ Ahi,
                     const __nv_bfloat16* __restrict__ Alo,
                     const __nv_bfloat16* __restrict__ Bhi,
                     const __nv_bfloat16* __restrict__ Blo,
                     const float* __restrict__ bias,
                     float* __restrict__ C)
{
    extern __shared__ __align__(128) char smem[];
    const uint32_t smem_base = smem_to_u32(smem);
    const int m0 = blockIdx.y * 128;
    const int n0 = blockIdx.x * 128;

    gemm_tile(Ahi, Alo, Bhi, Blo, DIM, m0, n0, smem_base,
        [&](float acc[2][8][4], int wm, int wn, int lane) {
#pragma unroll
            for (int mf = 0; mf < 2; mf++) {
                const int r0 = m0 + wm * 32 + mf * 16 + (lane >> 2);
#pragma unroll
                for (int nf = 0; nf < 8; nf++) {
                    const int col = n0 + wn * 64 + nf * 8 + (lane & 3) * 2;
                    float2 bv = *(const float2*)(bias + col);
                    *(float2*)(C + (size_t)r0 * DIM + col) =
                        make_float2(acc[mf][nf][0] + bv.x, acc[mf][nf][1] + bv.y);
                    *(float2*)(C + (size_t)(r0 + 8) * DIM + col) =
                        make_float2(acc[mf][nf][2] + bv.x, acc[mf][nf][3] + bv.y);
                }
            }
        });
}

// ---------------------------------------------------------------------------
// fp32 -> bf16 hi/lo split + weight transpose-split (unchanged)
// ---------------------------------------------------------------------------
__global__ __launch_bounds__(256)
void split_kernel(const float4* __restrict__ x, uint2* __restrict__ hi,
                  uint2* __restrict__ lo, int n4)
{
    int i = blockIdx.x * blockDim.x + threadIdx.x;
    if (i >= n4) return;
    float4 v = x[i];
    __nv_bfloat16 h[4], l[4];
    float f[4] = {v.x, v.y, v.z, v.w};
#pragma unroll
    for (int j = 0; j < 4; j++) {
        h[j] = __float2bfloat16(f[j]);
        l[j] = __float2bfloat16(f[j] - __bfloat162float(h[j]));
    }
    uint2 hp, lp;
    hp.x = ((uint32_t)*(uint16_t*)&h[1] << 16) | *(uint16_t*)&h[0];
    hp.y = ((uint32_t)*(uint16_t*)&h[3] << 16) | *(uint16_t*)&h[2];
    lp.x = ((uint32_t)*(uint16_t*)&l[1] << 16) | *(uint16_t*)&l[0];
    lp.y = ((uint32_t)*(uint16_t*)&l[3] << 16) | *(uint16_t*)&l[2];
    hi[i] = hp;
    lo[i] = lp;
}

__global__ __launch_bounds__(256)
void tsplit_kernel(const float* __restrict__ W, __nv_bfloat16* __restrict__ thi,
                   __nv_bfloat16* __restrict__ tlo, int K, int N)
{
    __shared__ float t[32][33];
    const int n0 = blockIdx.x * 32, k0 = blockIdx.y * 32;
    const int tx = threadIdx.x, ty = threadIdx.y;
#pragma unroll
    for (int i = 0; i < 4; i++)
        t[ty + 8 * i][tx] = W[(size_t)(k0 + ty + 8 * i) * N + n0 + tx];
    __syncthreads();
#pragma unroll
    for (int i = 0; i < 4; i++) {
        int r = ty + 8 * i;
        float v = t[tx][r];
        __nv_bfloat16 h = __float2bfloat16(v);
        size_t o = (size_t)(n0 + r) * K + k0 + tx;
        thi[o] = h;
        tlo[o] = __float2bfloat16(v - __bfloat162float(h));
    }
}

// ---------------------------------------------------------------------------
// Tensor-core attention, no-max softmax, row sums via ones-MMA.
// CTA = (b, h, 256-query tile); 8 warps x 32 rows. K chunks of 64.
// Q: fp16 hi/lo (scaled by 0.125*log2e), S = 3-term fp16 mma -> S in log2 units.
// P = ex2(S) -> fp16; O += P@(Vhi+Vlo); rowsum += P@ones.
// Smem rows padded to 144B.
// ---------------------------------------------------------------------------
#define AT_PADH  72                   // halves per padded row
#define AT_ROWB  144                  // bytes per row
#define AT_QBYTES (256 * AT_ROWB)     // 36864 per Q tensor
#define AT_TILEB  (64 * AT_ROWB)      // 9216 per KV tile
#define AT_STAGEB (4 * AT_TILEB)      // 36864
#define AT_SMEM_BYTES (2 * AT_QBYTES + 2 * AT_STAGEB)   // 147456
#define ONES_H2 0x3C003C00u

__global__ __launch_bounds__(256, 1)
void attn_tc_kernel(const float* __restrict__ dec,
                    const __half* __restrict__ khi, const __half* __restrict__ klo,
                    const __half* __restrict__ vhiT, const __half* __restrict__ vloT,
                    __nv_bfloat16* __restrict__ wahi, __nv_bfloat16* __restrict__ walo)
{
    extern __shared__ __align__(128) char smem[];
    const uint32_t smem_base = smem_to_u32(smem);
    const uint32_t qhiB = smem_base;
    const uint32_t qloB = smem_base + AT_QBYTES;
    const uint32_t kvB  = smem_base + 2 * AT_QBYTES;

    const int b  = blockIdx.z;
    const int h  = blockIdx.y;
    const int qt = blockIdx.x;            // 0..3, 256 queries each
    const int tid = threadIdx.x;
    const int wid = tid >> 5;
    const int lane = tid & 31;

    // ---- KV chunk loader (4 tiles x 64 rows x 128B) ----
    const __half* kh_base = khi + (size_t)(b * NN) * DIM + h * HD;
    const __half* kl_base = klo + (size_t)(b * NN) * DIM + h * HD;
    const __half* vh_base = vhiT + (size_t)(b * DIM + h * HD) * NN;
    const __half* vl_base = vloT + (size_t)(b * DIM + h * HD) * NN;

    auto load_kv = [&](int kt, int st) {
        const uint32_t dst0 = kvB + st * AT_STAGEB;
#pragma unroll
        for (int i = 0; i < 8; i++) {
            const int t = i >> 1;
            const int j = (i & 1) * 256 + tid;
            const int r = j >> 3;
            const int c = j & 7;
            const __half* src;
            if (t == 0)      src = kh_base + (size_t)(kt * 64 + r) * DIM + c * 8;
            else if (t == 1) src = kl_base + (size_t)(kt * 64 + r) * DIM + c * 8;
            else if (t == 2) src = vh_base + (size_t)r * NN + kt * 64 + c * 8;
            else             src = vl_base + (size_t)r * NN + kt * 64 + c * 8;
            CP_ASYNC_16(dst0 + t * AT_TILEB + r * AT_ROWB + c * 16, src);
        }
    };

    load_kv(0, 0);
    CP_COMMIT();

    // ---- Q load + scale + fp16 hi/lo split into smem ----
    {
        const float* qbase = dec + (size_t)(b * NN + qt * 256) * DIM + h * HD;
#pragma unroll
        for (int i = 0; i < 16; i++) {
            int idx = i * 256 + tid;
            int r = idx >> 4;          // 0..255
            int c4 = idx & 15;         // 0..15 (4 floats each)
            float4 q = *(const float4*)(qbase + (size_t)r * DIM + c4 * 4);
            float f[4] = {q.x * QSCALE, q.y * QSCALE, q.z * QSCALE, q.w * QSCALE};
            __half hh[4], hl[4];
#pragma unroll
            for (int e = 0; e < 4; e++) {
                hh[e] = __float2half_rn(f[e]);
                hl[e] = __float2half_rn(f[e] - __half2float(hh[e]));
            }
            uint2 hp, lp;
            hp.x = ((uint32_t)*(uint16_t*)&hh[1] << 16) | *(uint16_t*)&hh[0];
            hp.y = ((uint32_t)*(uint16_t*)&hh[3] << 16) | *(uint16_t*)&hh[2];
            lp.x = ((uint32_t)*(uint16_t*)&hl[1] << 16) | *(uint16_t*)&hl[0];
            lp.y = ((uint32_t)*(uint16_t*)&hl[3] << 16) | *(uint16_t*)&hl[2];
            uint32_t off = r * AT_ROWB + c4 * 8;
            *(uint2*)(smem + off) = hp;                    // Qhi
            *(uint2*)(smem + AT_QBYTES + off) = lp;        // Qlo
        }
    }
    __syncthreads();

    // ---- accumulators ----
    float oacc[2][8][4];
    float sumacc[2][4];
#pragma unroll
    for (int mf = 0; mf < 2; mf++) {
#pragma unroll
        for (int df = 0; df < 8; df++)
#pragma unroll
            for (int e = 0; e < 4; e++) oacc[mf][df][e] = 0.f;
#pragma unroll
        for (int e = 0; e < 4; e++) sumacc[mf][e] = 0.f;
    }

    const int qrow = wid * 32;             // warp's Q rows within tile
    const int lrow = lane & 15;
    const int lcol = lane >> 4;

    for (int kt = 0; kt < NN / 64; kt++) {
        const int st = kt & 1;
        if (kt + 1 < NN / 64) {
            load_kv(kt + 1, st ^ 1);
            CP_COMMIT();
            CP_WAIT1();
        } else {
            CP_WAIT0();
        }
        __syncthreads();

        const uint32_t khB = kvB + st * AT_STAGEB;
        const uint32_t klB = khB + AT_TILEB;
        const uint32_t vhB = khB + 2 * AT_TILEB;
        const uint32_t vlB = khB + 3 * AT_TILEB;

        // ---- S = Q @ K^T (3-term fp16), S in log2 units ----
        float sacc[2][8][4];
#pragma unroll
        for (int mf = 0; mf < 2; mf++)
#pragma unroll
            for (int nf = 0; nf < 8; nf++)
#pragma unroll
                for (int e = 0; e < 4; e++) sacc[mf][nf][e] = 0.f;

#pragma unroll
        for (int ks = 0; ks < 4; ks++) {
            const uint32_t kboff = (ks * 2 + lcol) * 16;
            uint32_t aqh[2][4], aql[2][4];
#pragma unroll
            for (int mf = 0; mf < 2; mf++) {
                uint32_t qoff = (qrow + mf * 16 + lrow) * AT_ROWB + kboff;
                ldm_x4(qhiB + qoff, aqh[mf][0], aqh[mf][1], aqh[mf][2], aqh[mf][3]);
                ldm_x4(qloB + qoff, aql[mf][0], aql[mf][1], aql[mf][2], aql[mf][3]);
            }
#pragma unroll
            for (int np = 0; np < 4; np++) {
                uint32_t roff = (np * 16 + lrow) * AT_ROWB + kboff;
                uint32_t kh[4], kl[4];
                ldm_x4(khB + roff, kh[0], kh[1], kh[2], kh[3]);
                ldm_x4(klB + roff, kl[0], kl[1], kl[2], kl[3]);
#pragma unroll
                for (int mf = 0; mf < 2; mf++)
#pragma unroll
                    for (int sub = 0; sub < 2; sub++) {
                        float* c = sacc[mf][np * 2 + sub];
                        mma_f16(c, aqh[mf][0], aqh[mf][1], aqh[mf][2], aqh[mf][3],
                                kh[sub], kh[sub + 2]);
                        mma_f16(c, aqh[mf][0], aqh[mf][1], aqh[mf][2], aqh[mf][3],
                                kl[sub], kl[sub + 2]);
                        mma_f16(c, aql[mf][0], aql[mf][1], aql[mf][2], aql[mf][3],
                                kh[sub], kh[sub + 2]);
                    }
            }
        }

        // ---- P = 2^S (fp16), then O += P@V, rowsum += P@ones ----
#pragma unroll
        for (int kt2 = 0; kt2 < 4; kt2++) {
            uint32_t pa[2][4];
#pragma unroll
            for (int mf = 0; mf < 2; mf++) {
                float* s0 = sacc[mf][kt2 * 2];
                float* s1 = sacc[mf][kt2 * 2 + 1];
                pa[mf][0] = packh2(ex2f(s0[0]), ex2f(s0[1]));
                pa[mf][1] = packh2(ex2f(s0[2]), ex2f(s0[3]));
                pa[mf][2] = packh2(ex2f(s1[0]), ex2f(s1[1]));
                pa[mf][3] = packh2(ex2f(s1[2]), ex2f(s1[3]));
            }
            const uint32_t cboff = (kt2 * 2 + lcol) * 16;
#pragma unroll
            for (int dp = 0; dp < 4; dp++) {
                uint32_t roff = (dp * 16 + lrow) * AT_ROWB + cboff;
                uint32_t vh[4], vl[4];
                ldm_x4(vhB + roff, vh[0], vh[1], vh[2], vh[3]);
                ldm_x4(vlB + roff, vl[0], vl[1], vl[2], vl[3]);
#pragma unroll
                for (int mf = 0; mf < 2; mf++)
#pragma unroll
                    for (int sub = 0; sub < 2; sub++) {
                        float* c = oacc[mf][dp * 2 + sub];
                        mma_f16(c, pa[mf][0], pa[mf][1], pa[mf][2], pa[mf][3],
                                vh[sub], vh[sub + 2]);
                        mma_f16(c, pa[mf][0], pa[mf][1], pa[mf][2], pa[mf][3],
                                vl[sub], vl[sub + 2]);
                    }
            }
#pragma unroll
            for (int mf = 0; mf < 2; mf++)
                mma_f16(sumacc[mf], pa[mf][0], pa[mf][1], pa[mf][2], pa[mf][3],
                        ONES_H2, ONES_H2);
        }
        __syncthreads();
    }

    // ---- Epilogue: normalize, split to bf16 hi/lo, store wa [B,N,DIM] ----
#pragma unroll
    for (int mf = 0; mf < 2; mf++) {
        const float inv0 = 1.f / sumacc[mf][0];
        const float inv1 = 1.f / sumacc[mf][2];
        const int row = b * NN + qt * 256 + qrow + mf * 16 + (lane >> 2);
#pragma unroll
        for (int df = 0; df < 8; df++) {
            const int col = h * HD + df * 8 + (lane & 3) * 2;
            float o0 = oacc[mf][df][0] * inv0, o1 = oacc[mf][df][1] * inv0;
            float o2 = oacc[mf][df][2] * inv1, o3 = oacc[mf][df][3] * inv1;
            __nv_bfloat16 h0 = __float2bfloat16(o0), h1 = __float2bfloat16(o1);
            __nv_bfloat16 h2 = __float2bfloat16(o2), h3 = __float2bfloat16(o3);
            __nv_bfloat16 l0 = __float2bfloat16(o0 - __bfloat162float(h0));
            __nv_bfloat16 l1 = __float2bfloat16(o1 - __bfloat162float(h1));
            __nv_bfloat16 l2 = __float2bfloat16(o2 - __bfloat162float(h2));
            __nv_bfloat16 l3 = __float2bfloat16(o3 - __bfloat162float(h3));
            uint32_t hp0 = ((uint32_t)*(uint16_t*)&h1 << 16) | *(uint16_t*)&h0;
            uint32_t hp1 = ((uint32_t)*(uint16_t*)&h3 << 16) | *(uint16_t*)&h2;
            uint32_t lp0 = ((uint32_t)*(uint16_t*)&l1 << 16) | *(uint16_t*)&l0;
            uint32_t lp1 = ((uint32_t)*(uint16_t*)&l3 << 16) | *(uint16_t*)&l2;
            *(uint32_t*)(wahi + (size_t)row * DIM + col) = hp0;
            *(uint32_t*)(wahi + (size_t)(row + 8) * DIM + col) = hp1;
            *(uint32_t*)(walo + (size_t)row * DIM + col) = lp0;
            *(uint32_t*)(walo + (size_t)(row + 8) * DIM + col) = lp1;
        }
    }
}

// ---------------------------------------------------------------------------
extern "C" void kernel_launch(void* const* d_in, const int* in_sizes, int n_in,
                              void* d_out, int out_size)
{
    (void)in_sizes; (void)n_in; (void)out_size;
    const float* en    = (const float*)d_in[0];
    const float* dec   = (const float*)d_in[1];
    const float* Wkv   = (const float*)d_in[2];
    const float* bkv   = (const float*)d_in[3];
    const float* Wproj = (const float*)d_in[4];
    const float* bproj = (const float*)d_in[5];
    float* out = (float*)d_out;

    __nv_bfloat16 *enhi, *enlo, *wahi, *walo, *wkvthi, *wkvtlo, *wpthi, *wptlo;
    __half *khi, *klo, *vhiT, *vloT;
    cudaGetSymbolAddress((void**)&enhi, g_enhi);
    cudaGetSymbolAddress((void**)&enlo, g_enlo);
    cudaGetSymbolAddress((void**)&wahi, g_wahi);
    cudaGetSymbolAddress((void**)&walo, g_walo);
    cudaGetSymbolAddress((void**)&wkvthi, g_Wkvthi);
    cudaGetSymbolAddress((void**)&wkvtlo, g_Wkvtlo);
    cudaGetSymbolAddress((void**)&wpthi, g_Wpthi);
    cudaGetSymbolAddress((void**)&wptlo, g_Wptlo);
    cudaGetSymbolAddress((void**)&khi, g_khi);
    cudaGetSymbolAddress((void**)&klo, g_klo);
    cudaGetSymbolAddress((void**)&vhiT, g_vhiT);
    cudaGetSymbolAddress((void**)&vloT, g_vloT);

    cudaFuncSetAttribute(gemm_kv_kernel,
                         cudaFuncAttributeMaxDynamicSharedMemorySize, GT_SMEM_BYTES);
    cudaFuncSetAttribute(gemm_out_kernel,
                         cudaFuncAttributeMaxDynamicSharedMemorySize, GT_SMEM_BYTES);
    cudaFuncSetAttribute(attn_tc_kernel,
                         cudaFuncAttributeMaxDynamicSharedMemorySize, AT_SMEM_BYTES);

    // 0) splits
    {
        int n4 = M_TOTAL * DIM / 4;
        split_kernel<<<n4 / 256, 256>>>((const float4*)en, (uint2*)enhi,
                                        (uint2*)enlo, n4);
    }
    tsplit_kernel<<<dim3(KV_N / 32, DIM / 32), dim3(32, 8)>>>(
        Wkv, wkvthi, wkvtlo, DIM, KV_N);
    tsplit_kernel<<<dim3(DIM / 32, DIM / 32), dim3(32, 8)>>>(
        Wproj, wpthi, wptlo, DIM, DIM);

    // 1) kv projection -> K/V fp16 hi/lo (V transposed)
    gemm_kv_kernel<<<dim3(KV_N / 128, M_TOTAL / 128), 256, GT_SMEM_BYTES>>>(
        enhi, enlo, wkvthi, wkvtlo, bkv, khi, klo, vhiT, vloT);

    // 2) tensor-core attention -> wa (bf16 hi/lo)
    attn_tc_kernel<<<dim3(NN / 256, NH, BB), 256, AT_SMEM_BYTES>>>(
        dec, khi, klo, vhiT, vloT, wahi, walo);

    // 3) output projection
    gemm_out_kernel<<<dim3(DIM / 128, M_TOTAL / 128), 256, GT_SMEM_BYTES>>>(
        wahi, walo, wpthi, wptlo, bproj, out);
}

// round 5
// speedup vs baseline: 3.0998x; 1.3217x over previous
#include <cuda_runtime.h>
#include <cuda_bf16.h>
#include <cuda_fp16.h>
#include <math.h>
#include <stdint.h>

// Problem constants
#define BB   8
#define NN   1024
#define DIM  768
#define NH   12
#define HD   64

#define M_TOTAL (BB*NN)          // 8192
#define KV_N    (2*DIM)          // 1536

// 0.125 * log2(e): folded into Q so exp(s*0.125) = 2^(S_acc)
#define QSCALE 0.180336880596349f

// ---------------------------------------------------------------------------
// Scratch (device globals)
// ---------------------------------------------------------------------------
__device__ __align__(256) __half g_enhi[M_TOTAL * DIM];
__device__ __align__(256) __half g_enlo[M_TOTAL * DIM];
__device__ __align__(256) __half g_wahi[M_TOTAL * DIM];
__device__ __align__(256) __half g_walo[M_TOTAL * DIM];
__device__ __align__(256) __half g_Wkvt[KV_N * DIM];   // [1536][768] (N,K) fp16
__device__ __align__(256) __half g_Wpt[DIM * DIM];     // [768][768]  (N,K) fp16

// K: [8192][768] fp16 (seq-major, head-d contiguous)
__device__ __align__(256) __half g_k[M_TOTAL * DIM];
// V transposed: [B][768 d][1024 seq] fp16 hi/lo
__device__ __align__(256) __half g_vhiT[BB * DIM * NN];
__device__ __align__(256) __half g_vloT[BB * DIM * NN];

// ---------------------------------------------------------------------------
// Low-level helpers
// ---------------------------------------------------------------------------
__device__ __forceinline__ uint32_t smem_to_u32(const void* smem_ptr) {
    uint32_t addr;
    asm("{ .reg .u64 tmp; cvta.to.shared.u64 tmp, %1; cvt.u32.u64 %0, tmp; }"
        : "=r"(addr) : "l"(smem_ptr));
    return addr;
}

#define CP_ASYNC_16(dst_u32, src_ptr) \
    asm volatile("cp.async.cg.shared.global [%0], [%1], 16;" \
                 :: "r"(dst_u32), "l"(src_ptr))
#define CP_COMMIT() asm volatile("cp.async.commit_group;" ::: "memory")
#define CP_WAIT0()  asm volatile("cp.async.wait_group 0;" ::: "memory")
#define CP_WAIT1()  asm volatile("cp.async.wait_group 1;" ::: "memory")

__device__ __forceinline__ void ldm_x4(uint32_t addr, uint32_t& r0, uint32_t& r1,
                                       uint32_t& r2, uint32_t& r3) {
    asm volatile("ldmatrix.sync.aligned.m8n8.x4.shared.b16 {%0,%1,%2,%3}, [%4];"
                 : "=r"(r0), "=r"(r1), "=r"(r2), "=r"(r3) : "r"(addr));
}

__device__ __forceinline__ void mma_f16(float* c, uint32_t a0, uint32_t a1,
                                        uint32_t a2, uint32_t a3,
                                        uint32_t b0, uint32_t b1) {
    asm volatile(
        "mma.sync.aligned.m16n8k16.row.col.f32.f16.f16.f32 "
        "{%0,%1,%2,%3}, {%4,%5,%6,%7}, {%8,%9}, {%0,%1,%2,%3};"
        : "+f"(c[0]), "+f"(c[1]), "+f"(c[2]), "+f"(c[3])
        : "r"(a0), "r"(a1), "r"(a2), "r"(a3), "r"(b0), "r"(b1));
}

__device__ __forceinline__ float ex2f(float x) {
    float y;
    asm("ex2.approx.f32 %0, %1;" : "=f"(y) : "f"(x));
    return y;
}

__device__ __forceinline__ uint32_t packh2(float lo, float hi) {
    half2 h = __floats2half2_rn(lo, hi);
    return *reinterpret_cast<uint32_t*>(&h);
}

__device__ __forceinline__ uint32_t pack2u(__half a, __half b) {
    return ((uint32_t)*(uint16_t*)&b << 16) | *(uint16_t*)&a;
}

// ---------------------------------------------------------------------------
// GEMM tile machinery (fp16 A hi/lo 2-term, fp16 B single, BK=32)
//   C[128,128] = (Ahi+Alo)[128,K] @ B^T[128,K]
// 8 warps (4m x 2n), warp tile 32x64, 2-stage cp.async pipeline.
// Smem rows: 32 halves = 64B padded to 80B; 16B-chunk swizzle c ^= (r&3).
// Stage = 3 tensors * 128 rows * 80B = 30720 B; 2 stages = 61440 B.
// ---------------------------------------------------------------------------
#define GT_SMEM_BYTES 61440
#define TILE_STRIDE   80
#define TENSOR_BYTES  (128 * TILE_STRIDE)   // 10240
#define STAGE_BYTES   (3 * TENSOR_BYTES)    // 30720

__device__ __forceinline__ uint32_t tile_addr(uint32_t base, int r, int kb16) {
    return base + r * TILE_STRIDE + ((kb16 ^ (r & 3)) << 4);
}

template <typename EpilogueFn>
__device__ __forceinline__ void gemm_tile(
    const __half* Ahi, const __half* Alo, const __half* B,
    int K, int m0, int n0, uint32_t smem_base, EpilogueFn epi)
{
    const int tid  = threadIdx.x;
    const int lane = tid & 31;

    const __half* srcs[3] = {
        Ahi + (size_t)m0 * K, Alo + (size_t)m0 * K, B + (size_t)n0 * K };

    auto load_chunk = [&](int chunk, int s) {
        const int k0 = chunk * 32;
        const uint32_t sbase = smem_base + s * STAGE_BYTES;
#pragma unroll
        for (int i = 0; i < 6; i++) {
            int idx = i * 256 + tid;
            int t = idx >> 9;
            int j = idx & 511;
            int r = j >> 2;
            int c = j & 3;
            const __half* src = srcs[t] + (size_t)r * K + k0 + c * 8;
            CP_ASYNC_16(tile_addr(sbase + t * TENSOR_BYTES, r, c), src);
        }
    };

    float acc[2][8][4];
#pragma unroll
    for (int mf = 0; mf < 2; mf++)
#pragma unroll
        for (int nf = 0; nf < 8; nf++)
#pragma unroll
            for (int e = 0; e < 4; e++) acc[mf][nf][e] = 0.f;

    const int wid = tid >> 5;
    const int wm  = wid & 3;
    const int wn  = wid >> 2;
    const int i8   = lane & 7;
    const int quad = lane >> 3;
    const int qr   = (quad & 1) << 3;
    const int qc   = quad >> 1;

    const int NCHUNK = K >> 5;

    load_chunk(0, 0);
    CP_COMMIT();

    for (int ch = 0; ch < NCHUNK; ch++) {
        const int s = ch & 1;
        if (ch + 1 < NCHUNK) {
            load_chunk(ch + 1, s ^ 1);
            CP_COMMIT();
            CP_WAIT1();
        } else {
            CP_WAIT0();
        }
        __syncthreads();

        const uint32_t sbase = smem_base + s * STAGE_BYTES;
        const uint32_t aHiB = sbase;
        const uint32_t aLoB = sbase + TENSOR_BYTES;
        const uint32_t bB   = sbase + 2 * TENSOR_BYTES;

#pragma unroll
        for (int kf = 0; kf < 2; kf++) {
            const int kb = kf * 2 + qc;
            uint32_t ah[2][4], al[2][4];
#pragma unroll
            for (int mf = 0; mf < 2; mf++) {
                int r = wm * 32 + mf * 16 + i8 + qr;
                ldm_x4(tile_addr(aHiB, r, kb), ah[mf][0], ah[mf][1], ah[mf][2], ah[mf][3]);
                ldm_x4(tile_addr(aLoB, r, kb), al[mf][0], al[mf][1], al[mf][2], al[mf][3]);
            }
            uint32_t bf[4][4];
#pragma unroll
            for (int nf2 = 0; nf2 < 4; nf2++) {
                int r = wn * 64 + nf2 * 16 + i8 + qr;
                ldm_x4(tile_addr(bB, r, kb), bf[nf2][0], bf[nf2][1], bf[nf2][2], bf[nf2][3]);
            }
#pragma unroll
            for (int mf = 0; mf < 2; mf++)
#pragma unroll
                for (int nf = 0; nf < 8; nf++) {
                    const int nf2 = nf >> 1, od = nf & 1;
                    float* c = acc[mf][nf];
                    mma_f16(c, ah[mf][0], ah[mf][1], ah[mf][2], ah[mf][3],
                            bf[nf2][od], bf[nf2][od + 2]);
                    mma_f16(c, al[mf][0], al[mf][1], al[mf][2], al[mf][3],
                            bf[nf2][od], bf[nf2][od + 2]);
                }
        }
        __syncthreads();
    }
    epi(acc, wm, wn, lane);
}

// GEMM1: kv projection, epilogue writes K (fp16) and V (transposed fp16 hi/lo)
__global__ __launch_bounds__(256, 2)
void gemm_kv_kernel(const __half* __restrict__ Ahi, const __half* __restrict__ Alo,
                    const __half* __restrict__ B, const float* __restrict__ bias,
                    __half* __restrict__ kk,
                    __half* __restrict__ vhiT, __half* __restrict__ vloT)
{
    extern __shared__ __align__(128) char smem[];
    const uint32_t smem_base = smem_to_u32(smem);
    const int m0 = blockIdx.y * 128;
    const int n0 = blockIdx.x * 128;
    const bool isV = (n0 >= DIM);

    gemm_tile(Ahi, Alo, B, DIM, m0, n0, smem_base,
        [&](float acc[2][8][4], int wm, int wn, int lane) {
#pragma unroll
            for (int mf = 0; mf < 2; mf++) {
                const int r0 = m0 + wm * 32 + mf * 16 + (lane >> 2);
#pragma unroll
                for (int nf = 0; nf < 8; nf++) {
                    const int col = n0 + wn * 64 + nf * 8 + (lane & 3) * 2;
                    float2 bv = *(const float2*)(bias + col);
                    float c0 = acc[mf][nf][0] + bv.x;
                    float c1 = acc[mf][nf][1] + bv.y;
                    float c2 = acc[mf][nf][2] + bv.x;
                    float c3 = acc[mf][nf][3] + bv.y;
                    __half h0 = __float2half_rn(c0), h1 = __float2half_rn(c1);
                    __half h2 = __float2half_rn(c2), h3 = __float2half_rn(c3);
                    if (!isV) {
                        *(uint32_t*)(kk + (size_t)r0 * DIM + col) = pack2u(h0, h1);
                        *(uint32_t*)(kk + (size_t)(r0 + 8) * DIM + col) = pack2u(h2, h3);
                    } else {
                        __half l0 = __float2half_rn(c0 - __half2float(h0));
                        __half l1 = __float2half_rn(c1 - __half2float(h1));
                        __half l2 = __float2half_rn(c2 - __half2float(h2));
                        __half l3 = __float2half_rn(c3 - __half2float(h3));
                        const int d = col - DIM;
                        const int b = r0 >> 10, seq = r0 & 1023;
                        size_t o00 = ((size_t)(b * DIM + d)) * NN + seq;
                        size_t o10 = o00 + NN;          // d+1
                        vhiT[o00] = h0;      vhiT[o10] = h1;
                        vhiT[o00 + 8] = h2;  vhiT[o10 + 8] = h3;   // seq+8
                        vloT[o00] = l0;      vloT[o10] = l1;
                        vloT[o00 + 8] = l2;  vloT[o10 + 8] = l3;
                    }
                }
            }
        });
}

// GEMM2: output projection, fp32 out + bias
__global__ __launch_bounds__(256, 2)
void gemm_out_kernel(const __half* __restrict__ Ahi, const __half* __restrict__ Alo,
                     const __half* __restrict__ B, const float* __restrict__ bias,
                     float* __restrict__ C)
{
    extern __shared__ __align__(128) char smem[];
    const uint32_t smem_base = smem_to_u32(smem);
    const int m0 = blockIdx.y * 128;
    const int n0 = blockIdx.x * 128;

    gemm_tile(Ahi, Alo, B, DIM, m0, n0, smem_base,
        [&](float acc[2][8][4], int wm, int wn, int lane) {
#pragma unroll
            for (int mf = 0; mf < 2; mf++) {
                const int r0 = m0 + wm * 32 + mf * 16 + (lane >> 2);
#pragma unroll
                for (int nf = 0; nf < 8; nf++) {
                    const int col = n0 + wn * 64 + nf * 8 + (lane & 3) * 2;
                    float2 bv = *(const float2*)(bias + col);
                    *(float2*)(C + (size_t)r0 * DIM + col) =
                        make_float2(acc[mf][nf][0] + bv.x, acc[mf][nf][1] + bv.y);
                    *(float2*)(C + (size_t)(r0 + 8) * DIM + col) =
                        make_float2(acc[mf][nf][2] + bv.x, acc[mf][nf][3] + bv.y);
                }
            }
        });
}

// ---------------------------------------------------------------------------
// fp32 -> fp16 hi/lo split; weight transpose -> fp16 single
// ---------------------------------------------------------------------------
__global__ __launch_bounds__(256)
void split_kernel(const float4* __restrict__ x, uint2* __restrict__ hi,
                  uint2* __restrict__ lo, int n4)
{
    int i = blockIdx.x * blockDim.x + threadIdx.x;
    if (i >= n4) return;
    float4 v = x[i];
    __half h[4], l[4];
    float f[4] = {v.x, v.y, v.z, v.w};
#pragma unroll
    for (int j = 0; j < 4; j++) {
        h[j] = __float2half_rn(f[j]);
        l[j] = __float2half_rn(f[j] - __half2float(h[j]));
    }
    hi[i] = make_uint2(pack2u(h[0], h[1]), pack2u(h[2], h[3]));
    lo[i] = make_uint2(pack2u(l[0], l[1]), pack2u(l[2], l[3]));
}

__global__ __launch_bounds__(256)
void tsplit_kernel(const float* __restrict__ W, __half* __restrict__ t16,
                   int K, int N)
{
    __shared__ float t[32][33];
    const int n0 = blockIdx.x * 32, k0 = blockIdx.y * 32;
    const int tx = threadIdx.x, ty = threadIdx.y;
#pragma unroll
    for (int i = 0; i < 4; i++)
        t[ty + 8 * i][tx] = W[(size_t)(k0 + ty + 8 * i) * N + n0 + tx];
    __syncthreads();
#pragma unroll
    for (int i = 0; i < 4; i++) {
        int r = ty + 8 * i;
        t16[(size_t)(n0 + r) * K + k0 + tx] = __float2half_rn(t[tx][r]);
    }
}

// ---------------------------------------------------------------------------
// Tensor-core attention, no-max softmax, row sums via ones-MMA.
// CTA = (b, h, 256-query tile); 8 warps x 32 rows. K chunks of 64.
// Q fp16 hi/lo (pre-scaled, fragments hoisted), K fp16 single,
// P = ex2(S) fp16, V fp16 hi/lo 2-term, rowsum via ones.
// ---------------------------------------------------------------------------
#define AT_ROWB  144                  // bytes per padded row
#define AT_QBYTES (256 * AT_ROWB)     // 36864 per Q tensor
#define AT_TILEB  (64 * AT_ROWB)      // 9216 per KV tile
#define AT_STAGEB (3 * AT_TILEB)      // 27648 (K, Vhi, Vlo)
#define AT_SMEM_BYTES (2 * AT_QBYTES + 2 * AT_STAGEB)   // 129024
#define ONES_H2 0x3C003C00u

__global__ __launch_bounds__(256, 1)
void attn_tc_kernel(const float* __restrict__ dec,
                    const __half* __restrict__ kk,
                    const __half* __restrict__ vhiT, const __half* __restrict__ vloT,
                    __half* __restrict__ wahi, __half* __restrict__ walo)
{
    extern __shared__ __align__(128) char smem[];
    const uint32_t smem_base = smem_to_u32(smem);
    const uint32_t qhiB = smem_base;
    const uint32_t qloB = smem_base + AT_QBYTES;
    const uint32_t kvB  = smem_base + 2 * AT_QBYTES;

    const int b  = blockIdx.z;
    const int h  = blockIdx.y;
    const int qt = blockIdx.x;            // 0..3, 256 queries each
    const int tid = threadIdx.x;
    const int wid = tid >> 5;
    const int lane = tid & 31;

    const __half* k_base  = kk + (size_t)(b * NN) * DIM + h * HD;
    const __half* vh_base = vhiT + (size_t)(b * DIM + h * HD) * NN;
    const __half* vl_base = vloT + (size_t)(b * DIM + h * HD) * NN;

    auto load_kv = [&](int kt, int st) {
        const uint32_t dst0 = kvB + st * AT_STAGEB;
#pragma unroll
        for (int i = 0; i < 6; i++) {
            const int idx = i * 256 + tid;
            const int t = idx >> 9;
            const int j = idx & 511;
            const int r = j >> 3;
            const int c = j & 7;
            const __half* src;
            if (t == 0)      src = k_base + (size_t)(kt * 64 + r) * DIM + c * 8;
            else if (t == 1) src = vh_base + (size_t)r * NN + kt * 64 + c * 8;
            else             src = vl_base + (size_t)r * NN + kt * 64 + c * 8;
            CP_ASYNC_16(dst0 + t * AT_TILEB + r * AT_ROWB + c * 16, src);
        }
    };

    load_kv(0, 0);
    CP_COMMIT();

    // ---- Q load + scale + fp16 hi/lo split into smem ----
    {
        const float* qbase = dec + (size_t)(b * NN + qt * 256) * DIM + h * HD;
#pragma unroll
        for (int i = 0; i < 16; i++) {
            int idx = i * 256 + tid;
            int r = idx >> 4;          // 0..255
            int c4 = idx & 15;
            float4 q = *(const float4*)(qbase + (size_t)r * DIM + c4 * 4);
            float f[4] = {q.x * QSCALE, q.y * QSCALE, q.z * QSCALE, q.w * QSCALE};
            __half hh[4], hl[4];
#pragma unroll
            for (int e = 0; e < 4; e++) {
                hh[e] = __float2half_rn(f[e]);
                hl[e] = __float2half_rn(f[e] - __half2float(hh[e]));
            }
            uint32_t off = r * AT_ROWB + c4 * 8;
            *(uint2*)(smem + off) = make_uint2(pack2u(hh[0], hh[1]), pack2u(hh[2], hh[3]));
            *(uint2*)(smem + AT_QBYTES + off) = make_uint2(pack2u(hl[0], hl[1]), pack2u(hl[2], hl[3]));
        }
    }
    __syncthreads();

    const int qrow = wid * 32;
    const int lrow = lane & 15;
    const int lcol = lane >> 4;

    // ---- hoist Q fragments (loop-invariant over kt) ----
    uint32_t qh[2][4][4], ql[2][4][4];
#pragma unroll
    for (int ks = 0; ks < 4; ks++) {
        const uint32_t kboff = (ks * 2 + lcol) * 16;
#pragma unroll
        for (int mf = 0; mf < 2; mf++) {
            uint32_t qoff = (qrow + mf * 16 + lrow) * AT_ROWB + kboff;
            ldm_x4(qhiB + qoff, qh[mf][ks][0], qh[mf][ks][1], qh[mf][ks][2], qh[mf][ks][3]);
            ldm_x4(qloB + qoff, ql[mf][ks][0], ql[mf][ks][1], ql[mf][ks][2], ql[mf][ks][3]);
        }
    }

    // ---- accumulators ----
    float oacc[2][8][4];
    float sumacc[2][4];
#pragma unroll
    for (int mf = 0; mf < 2; mf++) {
#pragma unroll
        for (int df = 0; df < 8; df++)
#pragma unroll
            for (int e = 0; e < 4; e++) oacc[mf][df][e] = 0.f;
#pragma unroll
        for (int e = 0; e < 4; e++) sumacc[mf][e] = 0.f;
    }

    for (int kt = 0; kt < NN / 64; kt++) {
        const int st = kt & 1;
        if (kt + 1 < NN / 64) {
            load_kv(kt + 1, st ^ 1);
            CP_COMMIT();
            CP_WAIT1();
        } else {
            CP_WAIT0();
        }
        __syncthreads();

        const uint32_t kB  = kvB + st * AT_STAGEB;
        const uint32_t vhB = kB + AT_TILEB;
        const uint32_t vlB = kB + 2 * AT_TILEB;

        // ---- S = Q @ K^T (2-term fp16), log2 units ----
        float sacc[2][8][4];
#pragma unroll
        for (int mf = 0; mf < 2; mf++)
#pragma unroll
            for (int nf = 0; nf < 8; nf++)
#pragma unroll
                for (int e = 0; e < 4; e++) sacc[mf][nf][e] = 0.f;

#pragma unroll
        for (int ks = 0; ks < 4; ks++) {
            const uint32_t kboff = (ks * 2 + lcol) * 16;
#pragma unroll
            for (int np = 0; np < 4; np++) {
                uint32_t roff = (np * 16 + lrow) * AT_ROWB + kboff;
                uint32_t kf[4];
                ldm_x4(kB + roff, kf[0], kf[1], kf[2], kf[3]);
#pragma unroll
                for (int mf = 0; mf < 2; mf++)
#pragma unroll
                    for (int sub = 0; sub < 2; sub++) {
                        float* c = sacc[mf][np * 2 + sub];
                        mma_f16(c, qh[mf][ks][0], qh[mf][ks][1], qh[mf][ks][2],
                                qh[mf][ks][3], kf[sub], kf[sub + 2]);
                        mma_f16(c, ql[mf][ks][0], ql[mf][ks][1], ql[mf][ks][2],
                                ql[mf][ks][3], kf[sub], kf[sub + 2]);
                    }
            }
        }

        // ---- P = 2^S (fp16), O += P@V (2-term), rowsum += P@ones ----
#pragma unroll
        for (int kt2 = 0; kt2 < 4; kt2++) {
            uint32_t pa[2][4];
#pragma unroll
            for (int mf = 0; mf < 2; mf++) {
                float* s0 = sacc[mf][kt2 * 2];
                float* s1 = sacc[mf][kt2 * 2 + 1];
                pa[mf][0] = packh2(ex2f(s0[0]), ex2f(s0[1]));
                pa[mf][1] = packh2(ex2f(s0[2]), ex2f(s0[3]));
                pa[mf][2] = packh2(ex2f(s1[0]), ex2f(s1[1]));
                pa[mf][3] = packh2(ex2f(s1[2]), ex2f(s1[3]));
            }
            const uint32_t cboff = (kt2 * 2 + lcol) * 16;
#pragma unroll
            for (int dp = 0; dp < 4; dp++) {
                uint32_t roff = (dp * 16 + lrow) * AT_ROWB + cboff;
                uint32_t vh[4], vl[4];
                ldm_x4(vhB + roff, vh[0], vh[1], vh[2], vh[3]);
                ldm_x4(vlB + roff, vl[0], vl[1], vl[2], vl[3]);
#pragma unroll
                for (int mf = 0; mf < 2; mf++)
#pragma unroll
                    for (int sub = 0; sub < 2; sub++) {
                        float* c = oacc[mf][dp * 2 + sub];
                        mma_f16(c, pa[mf][0], pa[mf][1], pa[mf][2], pa[mf][3],
                                vh[sub], vh[sub + 2]);
                        mma_f16(c, pa[mf][0], pa[mf][1], pa[mf][2], pa[mf][3],
                                vl[sub], vl[sub + 2]);
                    }
            }
#pragma unroll
            for (int mf = 0; mf < 2; mf++)
                mma_f16(sumacc[mf], pa[mf][0], pa[mf][1], pa[mf][2], pa[mf][3],
                        ONES_H2, ONES_H2);
        }
        __syncthreads();
    }

    // ---- Epilogue: normalize, split to fp16 hi/lo, store wa [B,N,DIM] ----
#pragma unroll
    for (int mf = 0; mf < 2; mf++) {
        const float inv0 = 1.f / sumacc[mf][0];
        const float inv1 = 1.f / sumacc[mf][2];
        const int row = b * NN + qt * 256 + qrow + mf * 16 + (lane >> 2);
#pragma unroll
        for (int df = 0; df < 8; df++) {
            const int col = h * HD + df * 8 + (lane & 3) * 2;
            float o0 = oacc[mf][df][0] * inv0, o1 = oacc[mf][df][1] * inv0;
            float o2 = oacc[mf][df][2] * inv1, o3 = oacc[mf][df][3] * inv1;
            __half h0 = __float2half_rn(o0), h1 = __float2half_rn(o1);
            __half h2 = __float2half_rn(o2), h3 = __float2half_rn(o3);
            __half l0 = __float2half_rn(o0 - __half2float(h0));
            __half l1 = __float2half_rn(o1 - __half2float(h1));
            __half l2 = __float2half_rn(o2 - __half2float(h2));
            __half l3 = __float2half_rn(o3 - __half2float(h3));
            *(uint32_t*)(wahi + (size_t)row * DIM + col) = pack2u(h0, h1);
            *(uint32_t*)(wahi + (size_t)(row + 8) * DIM + col) = pack2u(h2, h3);
            *(uint32_t*)(walo + (size_t)row * DIM + col) = pack2u(l0, l1);
            *(uint32_t*)(walo + (size_t)(row + 8) * DIM + col) = pack2u(l2, l3);
        }
    }
}

// ---------------------------------------------------------------------------
extern "C" void kernel_launch(void* const* d_in, const int* in_sizes, int n_in,
                              void* d_out, int out_size)
{
    (void)in_sizes; (void)n_in; (void)out_size;
    const float* en    = (const float*)d_in[0];
    const float* dec   = (const float*)d_in[1];
    const float* Wkv   = (const float*)d_in[2];
    const float* bkv   = (const float*)d_in[3];
    const float* Wproj = (const float*)d_in[4];
    const float* bproj = (const float*)d_in[5];
    float* out = (float*)d_out;

    __half *enhi, *enlo, *wahi, *walo, *wkvt, *wpt, *kk, *vhiT, *vloT;
    cudaGetSymbolAddress((void**)&enhi, g_enhi);
    cudaGetSymbolAddress((void**)&enlo, g_enlo);
    cudaGetSymbolAddress((void**)&wahi, g_wahi);
    cudaGetSymbolAddress((void**)&walo, g_walo);
    cudaGetSymbolAddress((void**)&wkvt, g_Wkvt);
    cudaGetSymbolAddress((void**)&wpt, g_Wpt);
    cudaGetSymbolAddress((void**)&kk, g_k);
    cudaGetSymbolAddress((void**)&vhiT, g_vhiT);
    cudaGetSymbolAddress((void**)&vloT, g_vloT);

    cudaFuncSetAttribute(gemm_kv_kernel,
                         cudaFuncAttributeMaxDynamicSharedMemorySize, GT_SMEM_BYTES);
    cudaFuncSetAttribute(gemm_out_kernel,
                         cudaFuncAttributeMaxDynamicSharedMemorySize, GT_SMEM_BYTES);
    cudaFuncSetAttribute(attn_tc_kernel,
                         cudaFuncAttributeMaxDynamicSharedMemorySize, AT_SMEM_BYTES);

    // 0) splits
    {
        int n4 = M_TOTAL * DIM / 4;
        split_kernel<<<n4 / 256, 256>>>((const float4*)en, (uint2*)enhi,
                                        (uint2*)enlo, n4);
    }
    tsplit_kernel<<<dim3(KV_N / 32, DIM / 32), dim3(32, 8)>>>(Wkv, wkvt, DIM, KV_N);
    tsplit_kernel<<<dim3(DIM / 32, DIM / 32), dim3(32, 8)>>>(Wproj, wpt, DIM, DIM);

    // 1) kv projection -> K fp16, V fp16 hi/lo (transposed)
    gemm_kv_kernel<<<dim3(KV_N / 128, M_TOTAL / 128), 256, GT_SMEM_BYTES>>>(
        enhi, enlo, wkvt, bkv, kk, vhiT, vloT);

    // 2) tensor-core attention -> wa (fp16 hi/lo)
    attn_tc_kernel<<<dim3(NN / 256, NH, BB), 256, AT_SMEM_BYTES>>>(
        dec, kk, vhiT, vloT, wahi, walo);

    // 3) output projection
    gemm_out_kernel<<<dim3(DIM / 128, M_TOTAL / 128), 256, GT_SMEM_BYTES>>>(
        wahi, walo, wpt, bproj, out);
}

// round 6
// speedup vs baseline: 4.6468x; 1.4991x over previous
#include <cuda_runtime.h>
#include <cuda_fp16.h>
#include <math.h>
#include <stdint.h>

// Problem constants
#define BB   8
#define NN   1024
#define DIM  768
#define NH   12
#define HD   64

#define M_TOTAL (BB*NN)          // 8192
#define KV_N    (2*DIM)          // 1536

// 0.125 * log2(e): folded into Q so exp(s*0.125) = 2^(S_acc)
#define QSCALE 0.180336880596349f

// ---------------------------------------------------------------------------
// Scratch (device globals)
// ---------------------------------------------------------------------------
__device__ __align__(256) __half g_en16[M_TOTAL * DIM];
__device__ __align__(256) __half g_wa16[M_TOTAL * DIM];
__device__ __align__(256) __half g_Wkvt[KV_N * DIM];   // [1536][768] (N,K) fp16
__device__ __align__(256) __half g_Wpt[DIM * DIM];     // [768][768]  (N,K) fp16
__device__ __align__(256) __half g_k[M_TOTAL * DIM];   // K [8192][768] fp16
__device__ __align__(256) __half g_vT[BB * DIM * NN];  // V^T [B][768 d][1024 seq]

// ---------------------------------------------------------------------------
// Low-level helpers
// ---------------------------------------------------------------------------
__device__ __forceinline__ uint32_t smem_to_u32(const void* smem_ptr) {
    uint32_t addr;
    asm("{ .reg .u64 tmp; cvta.to.shared.u64 tmp, %1; cvt.u32.u64 %0, tmp; }"
        : "=r"(addr) : "l"(smem_ptr));
    return addr;
}

#define CP_ASYNC_16(dst_u32, src_ptr) \
    asm volatile("cp.async.cg.shared.global [%0], [%1], 16;" \
                 :: "r"(dst_u32), "l"(src_ptr))
#define CP_COMMIT() asm volatile("cp.async.commit_group;" ::: "memory")
#define CP_WAIT0()  asm volatile("cp.async.wait_group 0;" ::: "memory")
#define CP_WAIT1()  asm volatile("cp.async.wait_group 1;" ::: "memory")

__device__ __forceinline__ void ldm_x4(uint32_t addr, uint32_t& r0, uint32_t& r1,
                                       uint32_t& r2, uint32_t& r3) {
    asm volatile("ldmatrix.sync.aligned.m8n8.x4.shared.b16 {%0,%1,%2,%3}, [%4];"
                 : "=r"(r0), "=r"(r1), "=r"(r2), "=r"(r3) : "r"(addr));
}

__device__ __forceinline__ void mma_f16(float* c, uint32_t a0, uint32_t a1,
                                        uint32_t a2, uint32_t a3,
                                        uint32_t b0, uint32_t b1) {
    asm volatile(
        "mma.sync.aligned.m16n8k16.row.col.f32.f16.f16.f32 "
        "{%0,%1,%2,%3}, {%4,%5,%6,%7}, {%8,%9}, {%0,%1,%2,%3};"
        : "+f"(c[0]), "+f"(c[1]), "+f"(c[2]), "+f"(c[3])
        : "r"(a0), "r"(a1), "r"(a2), "r"(a3), "r"(b0), "r"(b1));
}

__device__ __forceinline__ float ex2f(float x) {
    float y;
    asm("ex2.approx.f32 %0, %1;" : "=f"(y) : "f"(x));
    return y;
}

__device__ __forceinline__ uint32_t packh2(float lo, float hi) {
    half2 h = __floats2half2_rn(lo, hi);
    return *reinterpret_cast<uint32_t*>(&h);
}

__device__ __forceinline__ uint32_t pack2u(__half a, __half b) {
    return ((uint32_t)*(uint16_t*)&b << 16) | *(uint16_t*)&a;
}

// ---------------------------------------------------------------------------
// GEMM: C[256,128 tile] = A[256,K] @ B^T[128,K]   (single fp16, fp32 acc)
// 8 warps (4m x 2n), warp tile 64x64. BK=32, 2-stage cp.async pipeline.
// Smem rows: 32 halves = 64B padded to 80B; 16B-chunk swizzle c ^= (r&3).
// A tensor 256*80=20480B, B tensor 128*80=10240B; stage 30720B; 2 stages.
// ---------------------------------------------------------------------------
#define GT_SMEM_BYTES 61440
#define TILE_STRIDE   80
#define A_TENSOR_B    (256 * TILE_STRIDE)   // 20480
#define B_TENSOR_B    (128 * TILE_STRIDE)   // 10240
#define STAGE_BYTES   (A_TENSOR_B + B_TENSOR_B)  // 30720

__device__ __forceinline__ uint32_t tile_addr(uint32_t base, int r, int kb16) {
    return base + r * TILE_STRIDE + ((kb16 ^ (r & 3)) << 4);
}

template <typename EpilogueFn>
__device__ __forceinline__ void gemm_tile(
    const __half* A, const __half* B, int K, int m0, int n0,
    uint32_t smem_base, EpilogueFn epi)
{
    const int tid  = threadIdx.x;
    const int lane = tid & 31;

    const __half* Abase = A + (size_t)m0 * K;
    const __half* Bbase = B + (size_t)n0 * K;

    auto load_chunk = [&](int chunk, int s) {
        const int k0 = chunk * 32;
        const uint32_t sbase = smem_base + s * STAGE_BYTES;
#pragma unroll
        for (int i = 0; i < 6; i++) {
            int idx = i * 256 + tid;
            if (idx < 1024) {                      // A: 256 rows x 4 chunks
                int r = idx >> 2, c = idx & 3;
                CP_ASYNC_16(tile_addr(sbase, r, c),
                            Abase + (size_t)r * K + k0 + c * 8);
            } else {                               // B: 128 rows x 4 chunks
                int j = idx - 1024;
                int r = j >> 2, c = j & 3;
                CP_ASYNC_16(tile_addr(sbase + A_TENSOR_B, r, c),
                            Bbase + (size_t)r * K + k0 + c * 8);
            }
        }
    };

    float acc[4][8][4];
#pragma unroll
    for (int mf = 0; mf < 4; mf++)
#pragma unroll
        for (int nf = 0; nf < 8; nf++)
#pragma unroll
            for (int e = 0; e < 4; e++) acc[mf][nf][e] = 0.f;

    const int wid = tid >> 5;
    const int wm  = wid & 3;           // 4 warps in m (64 rows each)
    const int wn  = wid >> 2;          // 2 warps in n (64 cols each)
    const int i8   = lane & 7;
    const int quad = lane >> 3;
    const int qr   = (quad & 1) << 3;
    const int qc   = quad >> 1;

    const int NCHUNK = K >> 5;

    load_chunk(0, 0);
    CP_COMMIT();

    for (int ch = 0; ch < NCHUNK; ch++) {
        const int s = ch & 1;
        if (ch + 1 < NCHUNK) {
            load_chunk(ch + 1, s ^ 1);
            CP_COMMIT();
            CP_WAIT1();
        } else {
            CP_WAIT0();
        }
        __syncthreads();

        const uint32_t aB = smem_base + s * STAGE_BYTES;
        const uint32_t bB = aB + A_TENSOR_B;

#pragma unroll
        for (int kf = 0; kf < 2; kf++) {
            const int kb = kf * 2 + qc;
            uint32_t af[4][4];
#pragma unroll
            for (int mf = 0; mf < 4; mf++) {
                int r = wm * 64 + mf * 16 + i8 + qr;
                ldm_x4(tile_addr(aB, r, kb), af[mf][0], af[mf][1], af[mf][2], af[mf][3]);
            }
            uint32_t bf[4][4];
#pragma unroll
            for (int nf2 = 0; nf2 < 4; nf2++) {
                int r = wn * 64 + nf2 * 16 + i8 + qr;
                ldm_x4(tile_addr(bB, r, kb), bf[nf2][0], bf[nf2][1], bf[nf2][2], bf[nf2][3]);
            }
#pragma unroll
            for (int mf = 0; mf < 4; mf++)
#pragma unroll
                for (int nf = 0; nf < 8; nf++) {
                    const int nf2 = nf >> 1, od = nf & 1;
                    mma_f16(acc[mf][nf], af[mf][0], af[mf][1], af[mf][2], af[mf][3],
                            bf[nf2][od], bf[nf2][od + 2]);
                }
        }
        __syncthreads();
    }
    epi(acc, wm, wn, lane);
}

// GEMM1: kv projection -> K fp16 ([B*N,768]) and V fp16 transposed
__global__ __launch_bounds__(256)
void gemm_kv_kernel(const __half* __restrict__ A, const __half* __restrict__ B,
                    const float* __restrict__ bias,
                    __half* __restrict__ kk, __half* __restrict__ vT)
{
    extern __shared__ __align__(128) char smem[];
    const uint32_t smem_base = smem_to_u32(smem);
    const int m0 = blockIdx.y * 256;
    const int n0 = blockIdx.x * 128;
    const bool isV = (n0 >= DIM);

    gemm_tile(A, B, DIM, m0, n0, smem_base,
        [&](float acc[4][8][4], int wm, int wn, int lane) {
#pragma unroll
            for (int mf = 0; mf < 4; mf++) {
                const int r0 = m0 + wm * 64 + mf * 16 + (lane >> 2);
#pragma unroll
                for (int nf = 0; nf < 8; nf++) {
                    const int col = n0 + wn * 64 + nf * 8 + (lane & 3) * 2;
                    float2 bv = *(const float2*)(bias + col);
                    __half h0 = __float2half_rn(acc[mf][nf][0] + bv.x);
                    __half h1 = __float2half_rn(acc[mf][nf][1] + bv.y);
                    __half h2 = __float2half_rn(acc[mf][nf][2] + bv.x);
                    __half h3 = __float2half_rn(acc[mf][nf][3] + bv.y);
                    if (!isV) {
                        *(uint32_t*)(kk + (size_t)r0 * DIM + col) = pack2u(h0, h1);
                        *(uint32_t*)(kk + (size_t)(r0 + 8) * DIM + col) = pack2u(h2, h3);
                    } else {
                        const int d = col - DIM;
                        const int b = r0 >> 10, seq = r0 & 1023;
                        size_t o00 = ((size_t)(b * DIM + d)) * NN + seq;
                        size_t o10 = o00 + NN;          // d+1
                        vT[o00] = h0;      vT[o10] = h1;
                        vT[o00 + 8] = h2;  vT[o10 + 8] = h3;   // seq+8
                    }
                }
            }
        });
}

// GEMM2: output projection, fp32 out + bias
__global__ __launch_bounds__(256)
void gemm_out_kernel(const __half* __restrict__ A, const __half* __restrict__ B,
                     const float* __restrict__ bias, float* __restrict__ C)
{
    extern __shared__ __align__(128) char smem[];
    const uint32_t smem_base = smem_to_u32(smem);
    const int m0 = blockIdx.y * 256;
    const int n0 = blockIdx.x * 128;

    gemm_tile(A, B, DIM, m0, n0, smem_base,
        [&](float acc[4][8][4], int wm, int wn, int lane) {
#pragma unroll
            for (int mf = 0; mf < 4; mf++) {
                const int r0 = m0 + wm * 64 + mf * 16 + (lane >> 2);
#pragma unroll
                for (int nf = 0; nf < 8; nf++) {
                    const int col = n0 + wn * 64 + nf * 8 + (lane & 3) * 2;
                    float2 bv = *(const float2*)(bias + col);
                    *(float2*)(C + (size_t)r0 * DIM + col) =
                        make_float2(acc[mf][nf][0] + bv.x, acc[mf][nf][1] + bv.y);
                    *(float2*)(C + (size_t)(r0 + 8) * DIM + col) =
                        make_float2(acc[mf][nf][2] + bv.x, acc[mf][nf][3] + bv.y);
                }
            }
        });
}

// ---------------------------------------------------------------------------
// fp32 -> fp16 convert; weight transpose -> fp16
// ---------------------------------------------------------------------------
__global__ __launch_bounds__(256)
void conv16_kernel(const float4* __restrict__ x, uint2* __restrict__ o, int n4)
{
    int i = blockIdx.x * blockDim.x + threadIdx.x;
    if (i >= n4) return;
    float4 v = x[i];
    o[i] = make_uint2(packh2(v.x, v.y), packh2(v.z, v.w));
}

__global__ __launch_bounds__(256)
void tsplit_kernel(const float* __restrict__ W, __half* __restrict__ t16,
                   int K, int N)
{
    __shared__ float t[32][33];
    const int n0 = blockIdx.x * 32, k0 = blockIdx.y * 32;
    const int tx = threadIdx.x, ty = threadIdx.y;
#pragma unroll
    for (int i = 0; i < 4; i++)
        t[ty + 8 * i][tx] = W[(size_t)(k0 + ty + 8 * i) * N + n0 + tx];
    __syncthreads();
#pragma unroll
    for (int i = 0; i < 4; i++) {
        int r = ty + 8 * i;
        t16[(size_t)(n0 + r) * K + k0 + tx] = __float2half_rn(t[tx][r]);
    }
}

// ---------------------------------------------------------------------------
// Tensor-core attention, no-max softmax, row sums via ones-MMA.
// CTA = (b, h, 256-query tile); 8 warps x 32 q rows. KV chunks of 64.
// All single fp16: Q (pre-scaled, fragments hoisted), K, P=ex2(S), V^T.
// ---------------------------------------------------------------------------
#define AT_ROWB  144                  // bytes per padded row (64 halves + pad)
#define AT_QBYTES (256 * AT_ROWB)     // 36864
#define AT_TILEB  (64 * AT_ROWB)      // 9216
#define AT_STAGEB (2 * AT_TILEB)      // 18432 (K, V)
#define AT_SMEM_BYTES (AT_QBYTES + 2 * AT_STAGEB)   // 73728
#define ONES_H2 0x3C003C00u

__global__ __launch_bounds__(256, 1)
void attn_tc_kernel(const float* __restrict__ dec,
                    const __half* __restrict__ kk, const __half* __restrict__ vT,
                    __half* __restrict__ wa16)
{
    extern __shared__ __align__(128) char smem[];
    const uint32_t smem_base = smem_to_u32(smem);
    const uint32_t qB  = smem_base;
    const uint32_t kvB = smem_base + AT_QBYTES;

    const int b  = blockIdx.z;
    const int h  = blockIdx.y;
    const int qt = blockIdx.x;            // 0..3
    const int tid = threadIdx.x;
    const int wid = tid >> 5;
    const int lane = tid & 31;

    const __half* k_base = kk + (size_t)(b * NN) * DIM + h * HD;
    const __half* v_base = vT + (size_t)(b * DIM + h * HD) * NN;

    auto load_kv = [&](int kt, int st) {
        const uint32_t dst0 = kvB + st * AT_STAGEB;
#pragma unroll
        for (int i = 0; i < 4; i++) {
            const int idx = i * 256 + tid;
            const int t = idx >> 9;
            const int j = idx & 511;
            const int r = j >> 3;
            const int c = j & 7;
            const __half* src = (t == 0)
                ? k_base + (size_t)(kt * 64 + r) * DIM + c * 8
                : v_base + (size_t)r * NN + kt * 64 + c * 8;
            CP_ASYNC_16(dst0 + t * AT_TILEB + r * AT_ROWB + c * 16, src);
        }
    };

    load_kv(0, 0);
    CP_COMMIT();

    // ---- Q load + scale + fp16 into smem ----
    {
        const float* qbase = dec + (size_t)(b * NN + qt * 256) * DIM + h * HD;
#pragma unroll
        for (int i = 0; i < 16; i++) {
            int idx = i * 256 + tid;
            int r = idx >> 4;
            int c4 = idx & 15;
            float4 q = *(const float4*)(qbase + (size_t)r * DIM + c4 * 4);
            uint32_t off = r * AT_ROWB + c4 * 8;
            *(uint2*)(smem + off) = make_uint2(
                packh2(q.x * QSCALE, q.y * QSCALE),
                packh2(q.z * QSCALE, q.w * QSCALE));
        }
    }
    __syncthreads();

    const int qrow = wid * 32;
    const int lrow = lane & 15;
    const int lcol = lane >> 4;

    // ---- hoist Q fragments ----
    uint32_t qh[2][4][4];
#pragma unroll
    for (int ks = 0; ks < 4; ks++) {
        const uint32_t kboff = (ks * 2 + lcol) * 16;
#pragma unroll
        for (int mf = 0; mf < 2; mf++) {
            uint32_t qoff = (qrow + mf * 16 + lrow) * AT_ROWB + kboff;
            ldm_x4(qB + qoff, qh[mf][ks][0], qh[mf][ks][1], qh[mf][ks][2], qh[mf][ks][3]);
        }
    }

    float oacc[2][8][4];
    float sumacc[2][4];
#pragma unroll
    for (int mf = 0; mf < 2; mf++) {
#pragma unroll
        for (int df = 0; df < 8; df++)
#pragma unroll
            for (int e = 0; e < 4; e++) oacc[mf][df][e] = 0.f;
#pragma unroll
        for (int e = 0; e < 4; e++) sumacc[mf][e] = 0.f;
    }

    for (int kt = 0; kt < NN / 64; kt++) {
        const int st = kt & 1;
        if (kt + 1 < NN / 64) {
            load_kv(kt + 1, st ^ 1);
            CP_COMMIT();
            CP_WAIT1();
        } else {
            CP_WAIT0();
        }
        __syncthreads();

        const uint32_t kB = kvB + st * AT_STAGEB;
        const uint32_t vB = kB + AT_TILEB;

        // ---- S = Q @ K^T (log2 units) ----
        float sacc[2][8][4];
#pragma unroll
        for (int mf = 0; mf < 2; mf++)
#pragma unroll
            for (int nf = 0; nf < 8; nf++)
#pragma unroll
                for (int e = 0; e < 4; e++) sacc[mf][nf][e] = 0.f;

#pragma unroll
        for (int ks = 0; ks < 4; ks++) {
            const uint32_t kboff = (ks * 2 + lcol) * 16;
#pragma unroll
            for (int np = 0; np < 4; np++) {
                uint32_t roff = (np * 16 + lrow) * AT_ROWB + kboff;
                uint32_t kf[4];
                ldm_x4(kB + roff, kf[0], kf[1], kf[2], kf[3]);
#pragma unroll
                for (int mf = 0; mf < 2; mf++)
#pragma unroll
                    for (int sub = 0; sub < 2; sub++)
                        mma_f16(sacc[mf][np * 2 + sub],
                                qh[mf][ks][0], qh[mf][ks][1], qh[mf][ks][2],
                                qh[mf][ks][3], kf[sub], kf[sub + 2]);
            }
        }

        // ---- P = 2^S (fp16); O += P@V; rowsum += P@ones ----
#pragma unroll
        for (int kt2 = 0; kt2 < 4; kt2++) {
            uint32_t pa[2][4];
#pragma unroll
            for (int mf = 0; mf < 2; mf++) {
                float* s0 = sacc[mf][kt2 * 2];
                float* s1 = sacc[mf][kt2 * 2 + 1];
                pa[mf][0] = packh2(ex2f(s0[0]), ex2f(s0[1]));
                pa[mf][1] = packh2(ex2f(s0[2]), ex2f(s0[3]));
                pa[mf][2] = packh2(ex2f(s1[0]), ex2f(s1[1]));
                pa[mf][3] = packh2(ex2f(s1[2]), ex2f(s1[3]));
            }
            const uint32_t cboff = (kt2 * 2 + lcol) * 16;
#pragma unroll
            for (int dp = 0; dp < 4; dp++) {
                uint32_t roff = (dp * 16 + lrow) * AT_ROWB + cboff;
                uint32_t vf[4];
                ldm_x4(vB + roff, vf[0], vf[1], vf[2], vf[3]);
#pragma unroll
                for (int mf = 0; mf < 2; mf++)
#pragma unroll
                    for (int sub = 0; sub < 2; sub++)
                        mma_f16(oacc[mf][dp * 2 + sub],
                                pa[mf][0], pa[mf][1], pa[mf][2], pa[mf][3],
                                vf[sub], vf[sub + 2]);
            }
#pragma unroll
            for (int mf = 0; mf < 2; mf++)
                mma_f16(sumacc[mf], pa[mf][0], pa[mf][1], pa[mf][2], pa[mf][3],
                        ONES_H2, ONES_H2);
        }
        __syncthreads();
    }

    // ---- Epilogue: normalize, store wa fp16 [B,N,DIM] ----
#pragma unroll
    for (int mf = 0; mf < 2; mf++) {
        const float inv0 = 1.f / sumacc[mf][0];
        const float inv1 = 1.f / sumacc[mf][2];
        const int row = b * NN + qt * 256 + qrow + mf * 16 + (lane >> 2);
#pragma unroll
        for (int df = 0; df < 8; df++) {
            const int col = h * HD + df * 8 + (lane & 3) * 2;
            *(uint32_t*)(wa16 + (size_t)row * DIM + col) =
                packh2(oacc[mf][df][0] * inv0, oacc[mf][df][1] * inv0);
            *(uint32_t*)(wa16 + (size_t)(row + 8) * DIM + col) =
                packh2(oacc[mf][df][2] * inv1, oacc[mf][df][3] * inv1);
        }
    }
}

// ---------------------------------------------------------------------------
extern "C" void kernel_launch(void* const* d_in, const int* in_sizes, int n_in,
                              void* d_out, int out_size)
{
    (void)in_sizes; (void)n_in; (void)out_size;
    const float* en    = (const float*)d_in[0];
    const float* dec   = (const float*)d_in[1];
    const float* Wkv   = (const float*)d_in[2];
    const float* bkv   = (const float*)d_in[3];
    const float* Wproj = (const float*)d_in[4];
    const float* bproj = (const float*)d_in[5];
    float* out = (float*)d_out;

    __half *en16, *wa16, *wkvt, *wpt, *kk, *vT;
    cudaGetSymbolAddress((void**)&en16, g_en16);
    cudaGetSymbolAddress((void**)&wa16, g_wa16);
    cudaGetSymbolAddress((void**)&wkvt, g_Wkvt);
    cudaGetSymbolAddress((void**)&wpt, g_Wpt);
    cudaGetSymbolAddress((void**)&kk, g_k);
    cudaGetSymbolAddress((void**)&vT, g_vT);

    cudaFuncSetAttribute(gemm_kv_kernel,
                         cudaFuncAttributeMaxDynamicSharedMemorySize, GT_SMEM_BYTES);
    cudaFuncSetAttribute(gemm_out_kernel,
                         cudaFuncAttributeMaxDynamicSharedMemorySize, GT_SMEM_BYTES);
    cudaFuncSetAttribute(attn_tc_kernel,
                         cudaFuncAttributeMaxDynamicSharedMemorySize, AT_SMEM_BYTES);

    // 0) converts
    {
        int n4 = M_TOTAL * DIM / 4;
        conv16_kernel<<<n4 / 256, 256>>>((const float4*)en, (uint2*)en16, n4);
    }
    tsplit_kernel<<<dim3(KV_N / 32, DIM / 32), dim3(32, 8)>>>(Wkv, wkvt, DIM, KV_N);
    tsplit_kernel<<<dim3(DIM / 32, DIM / 32), dim3(32, 8)>>>(Wproj, wpt, DIM, DIM);

    // 1) kv projection -> K fp16, V^T fp16
    gemm_kv_kernel<<<dim3(KV_N / 128, M_TOTAL / 256), 256, GT_SMEM_BYTES>>>(
        en16, wkvt, bkv, kk, vT);

    // 2) tensor-core attention -> wa fp16
    attn_tc_kernel<<<dim3(NN / 256, NH, BB), 256, AT_SMEM_BYTES>>>(
        dec, kk, vT, wa16);

    // 3) output projection
    gemm_out_kernel<<<dim3(DIM / 128, M_TOTAL / 256), 256, GT_SMEM_BYTES>>>(
        wa16, wpt, bproj, out);
}

// round 7
// speedup vs baseline: 5.4101x; 1.1643x over previous
#include <cuda_runtime.h>
#include <cuda_fp16.h>
#include <math.h>
#include <stdint.h>

// Problem constants
#define BB   8
#define NN   1024
#define DIM  768
#define NH   12
#define HD   64

#define M_TOTAL (BB*NN)          // 8192
#define KV_N    (2*DIM)          // 1536

// 0.125 * log2(e): folded into Q so exp(s*0.125) = 2^(S_acc)
#define QSCALE 0.180336880596349f

// ---------------------------------------------------------------------------
// Scratch (device globals)
// ---------------------------------------------------------------------------
__device__ __align__(256) __half g_en16[M_TOTAL * DIM];
__device__ __align__(256) __half g_q16[M_TOTAL * DIM];    // dec * QSCALE, fp16
__device__ __align__(256) __half g_wa16[M_TOTAL * DIM];
__device__ __align__(256) __half g_Wkvt[KV_N * DIM];      // [1536][768] (N,K)
__device__ __align__(256) __half g_Wpt[DIM * DIM];        // [768][768]  (N,K)
__device__ __align__(256) __half g_k[M_TOTAL * DIM];      // K [8192][768]
__device__ __align__(256) __half g_vT[BB * DIM * NN];     // V^T [B][768][1024]

// ---------------------------------------------------------------------------
// Low-level helpers
// ---------------------------------------------------------------------------
__device__ __forceinline__ uint32_t smem_to_u32(const void* smem_ptr) {
    uint32_t addr;
    asm("{ .reg .u64 tmp; cvta.to.shared.u64 tmp, %1; cvt.u32.u64 %0, tmp; }"
        : "=r"(addr) : "l"(smem_ptr));
    return addr;
}

#define CP_ASYNC_16(dst_u32, src_ptr) \
    asm volatile("cp.async.cg.shared.global [%0], [%1], 16;" \
                 :: "r"(dst_u32), "l"(src_ptr))
#define CP_COMMIT() asm volatile("cp.async.commit_group;" ::: "memory")
#define CP_WAIT1()  asm volatile("cp.async.wait_group 1;" ::: "memory")

__device__ __forceinline__ void ldm_x4(uint32_t addr, uint32_t& r0, uint32_t& r1,
                                       uint32_t& r2, uint32_t& r3) {
    asm volatile("ldmatrix.sync.aligned.m8n8.x4.shared.b16 {%0,%1,%2,%3}, [%4];"
                 : "=r"(r0), "=r"(r1), "=r"(r2), "=r"(r3) : "r"(addr));
}

__device__ __forceinline__ void mma_f16(float* c, uint32_t a0, uint32_t a1,
                                        uint32_t a2, uint32_t a3,
                                        uint32_t b0, uint32_t b1) {
    asm volatile(
        "mma.sync.aligned.m16n8k16.row.col.f32.f16.f16.f32 "
        "{%0,%1,%2,%3}, {%4,%5,%6,%7}, {%8,%9}, {%0,%1,%2,%3};"
        : "+f"(c[0]), "+f"(c[1]), "+f"(c[2]), "+f"(c[3])
        : "r"(a0), "r"(a1), "r"(a2), "r"(a3), "r"(b0), "r"(b1));
}

__device__ __forceinline__ float ex2f(float x) {
    float y;
    asm("ex2.approx.f32 %0, %1;" : "=f"(y) : "f"(x));
    return y;
}

__device__ __forceinline__ uint32_t packh2(float lo, float hi) {
    half2 h = __floats2half2_rn(lo, hi);
    return *reinterpret_cast<uint32_t*>(&h);
}

// ---------------------------------------------------------------------------
// GEMM: C tile 128x128 = A[128,K] @ B^T[128,K]  (single fp16, fp32 acc)
// 128 threads, 4 warps (2m x 2n), warp tile 64x64. BK=32.
// 3-stage cp.async pipeline, one __syncthreads per chunk, 2 CTAs/SM.
// Smem rows: 32 halves = 64B padded to 80B; 16B-chunk swizzle c ^= (r&3).
// Stage = 2 * 128 * 80 = 20480 B; 3 stages = 61440 B.
// ---------------------------------------------------------------------------
#define TILE_STRIDE   80
#define T_TENSOR_B    (128 * TILE_STRIDE)   // 10240
#define STAGE_BYTES   (2 * T_TENSOR_B)      // 20480
#define GT_SMEM_BYTES (3 * STAGE_BYTES)     // 61440

__device__ __forceinline__ uint32_t tile_addr(uint32_t base, int r, int kb16) {
    return base + r * TILE_STRIDE + ((kb16 ^ (r & 3)) << 4);
}

template <typename EpilogueFn>
__device__ __forceinline__ void gemm_tile(
    const __half* A, const __half* B, int K, int m0, int n0,
    uint32_t smem_base, EpilogueFn epi)
{
    const int tid  = threadIdx.x;
    const int lane = tid & 31;

    const __half* Abase = A + (size_t)m0 * K;
    const __half* Bbase = B + (size_t)n0 * K;

    auto load_chunk = [&](int chunk, int s) {
        const int k0 = chunk * 32;
        const uint32_t sbase = smem_base + s * STAGE_BYTES;
#pragma unroll
        for (int i = 0; i < 8; i++) {
            int idx = i * 128 + tid;       // 0..1023
            int t = idx >> 9;              // 0 = A, 1 = B
            int j = idx & 511;
            int r = j >> 2, c = j & 3;
            const __half* src = (t == 0 ? Abase : Bbase) + (size_t)r * K + k0 + c * 8;
            CP_ASYNC_16(tile_addr(sbase + t * T_TENSOR_B, r, c), src);
        }
    };

    float acc[4][8][4];
#pragma unroll
    for (int mf = 0; mf < 4; mf++)
#pragma unroll
        for (int nf = 0; nf < 8; nf++)
#pragma unroll
            for (int e = 0; e < 4; e++) acc[mf][nf][e] = 0.f;

    const int wid = tid >> 5;
    const int wm  = wid & 1;           // 2 warps in m (64 rows each)
    const int wn  = wid >> 1;          // 2 warps in n (64 cols each)
    const int i8   = lane & 7;
    const int quad = lane >> 3;
    const int qr   = (quad & 1) << 3;
    const int qc   = quad >> 1;

    const int NCHUNK = K >> 5;

    load_chunk(0, 0); CP_COMMIT();
    load_chunk(1, 1); CP_COMMIT();

    for (int ch = 0; ch < NCHUNK; ch++) {
        const int s = ch % 3;
        CP_WAIT1();
        __syncthreads();

        const uint32_t aB = smem_base + s * STAGE_BYTES;
        const uint32_t bB = aB + T_TENSOR_B;

#pragma unroll
        for (int kf = 0; kf < 2; kf++) {
            const int kb = kf * 2 + qc;
            uint32_t af[4][4];
#pragma unroll
            for (int mf = 0; mf < 4; mf++) {
                int r = wm * 64 + mf * 16 + i8 + qr;
                ldm_x4(tile_addr(aB, r, kb), af[mf][0], af[mf][1], af[mf][2], af[mf][3]);
            }
            uint32_t bf[4][4];
#pragma unroll
            for (int nf2 = 0; nf2 < 4; nf2++) {
                int r = wn * 64 + nf2 * 16 + i8 + qr;
                ldm_x4(tile_addr(bB, r, kb), bf[nf2][0], bf[nf2][1], bf[nf2][2], bf[nf2][3]);
            }
#pragma unroll
            for (int mf = 0; mf < 4; mf++)
#pragma unroll
                for (int nf = 0; nf < 8; nf++) {
                    const int nf2 = nf >> 1, od = nf & 1;
                    mma_f16(acc[mf][nf], af[mf][0], af[mf][1], af[mf][2], af[mf][3],
                            bf[nf2][od], bf[nf2][od + 2]);
                }
        }

        if (ch + 2 < NCHUNK) load_chunk(ch + 2, (ch + 2) % 3);
        CP_COMMIT();   // empty group when no load: keeps wait counting exact
    }
    epi(acc, wm, wn, lane);
}

// GEMM1: kv projection -> K fp16 ([B*N,768]) and V fp16 transposed
__global__ __launch_bounds__(128, 2)
void gemm_kv_kernel(const __half* __restrict__ A, const __half* __restrict__ B,
                    const float* __restrict__ bias,
                    __half* __restrict__ kk, __half* __restrict__ vT)
{
    extern __shared__ __align__(128) char smem[];
    const uint32_t smem_base = smem_to_u32(smem);
    const int m0 = blockIdx.y * 128;
    const int n0 = blockIdx.x * 128;
    const bool isV = (n0 >= DIM);

    gemm_tile(A, B, DIM, m0, n0, smem_base,
        [&](float acc[4][8][4], int wm, int wn, int lane) {
#pragma unroll
            for (int mf = 0; mf < 4; mf++) {
                const int r0 = m0 + wm * 64 + mf * 16 + (lane >> 2);
#pragma unroll
                for (int nf = 0; nf < 8; nf++) {
                    const int col = n0 + wn * 64 + nf * 8 + (lane & 3) * 2;
                    float2 bv = *(const float2*)(bias + col);
                    __half h0 = __float2half_rn(acc[mf][nf][0] + bv.x);
                    __half h1 = __float2half_rn(acc[mf][nf][1] + bv.y);
                    __half h2 = __float2half_rn(acc[mf][nf][2] + bv.x);
                    __half h3 = __float2half_rn(acc[mf][nf][3] + bv.y);
                    if (!isV) {
                        *(uint32_t*)(kk + (size_t)r0 * DIM + col) =
                            ((uint32_t)*(uint16_t*)&h1 << 16) | *(uint16_t*)&h0;
                        *(uint32_t*)(kk + (size_t)(r0 + 8) * DIM + col) =
                            ((uint32_t)*(uint16_t*)&h3 << 16) | *(uint16_t*)&h2;
                    } else {
                        const int d = col - DIM;
                        const int b = r0 >> 10, seq = r0 & 1023;
                        size_t o00 = ((size_t)(b * DIM + d)) * NN + seq;
                        size_t o10 = o00 + NN;          // d+1
                        vT[o00] = h0;      vT[o10] = h1;
                        vT[o00 + 8] = h2;  vT[o10 + 8] = h3;   // seq+8
                    }
                }
            }
        });
}

// GEMM2: output projection, fp32 out + bias
__global__ __launch_bounds__(128, 2)
void gemm_out_kernel(const __half* __restrict__ A, const __half* __restrict__ B,
                     const float* __restrict__ bias, float* __restrict__ C)
{
    extern __shared__ __align__(128) char smem[];
    const uint32_t smem_base = smem_to_u32(smem);
    const int m0 = blockIdx.y * 128;
    const int n0 = blockIdx.x * 128;

    gemm_tile(A, B, DIM, m0, n0, smem_base,
        [&](float acc[4][8][4], int wm, int wn, int lane) {
#pragma unroll
            for (int mf = 0; mf < 4; mf++) {
                const int r0 = m0 + wm * 64 + mf * 16 + (lane >> 2);
#pragma unroll
                for (int nf = 0; nf < 8; nf++) {
                    const int col = n0 + wn * 64 + nf * 8 + (lane & 3) * 2;
                    float2 bv = *(const float2*)(bias + col);
                    *(float2*)(C + (size_t)r0 * DIM + col) =
                        make_float2(acc[mf][nf][0] + bv.x, acc[mf][nf][1] + bv.y);
                    *(float2*)(C + (size_t)(r0 + 8) * DIM + col) =
                        make_float2(acc[mf][nf][2] + bv.x, acc[mf][nf][3] + bv.y);
                }
            }
        });
}

// ---------------------------------------------------------------------------
// fp32 -> fp16 convert with scale; weight transpose -> fp16
// ---------------------------------------------------------------------------
__global__ __launch_bounds__(256)
void conv16_kernel(const float4* __restrict__ x, uint2* __restrict__ o,
                   float scale, int n4)
{
    int i = blockIdx.x * blockDim.x + threadIdx.x;
    if (i >= n4) return;
    float4 v = x[i];
    o[i] = make_uint2(packh2(v.x * scale, v.y * scale),
                      packh2(v.z * scale, v.w * scale));
}

__global__ __launch_bounds__(256)
void tsplit_kernel(const float* __restrict__ W, __half* __restrict__ t16,
                   int K, int N)
{
    __shared__ float t[32][33];
    const int n0 = blockIdx.x * 32, k0 = blockIdx.y * 32;
    const int tx = threadIdx.x, ty = threadIdx.y;
#pragma unroll
    for (int i = 0; i < 4; i++)
        t[ty + 8 * i][tx] = W[(size_t)(k0 + ty + 8 * i) * N + n0 + tx];
    __syncthreads();
#pragma unroll
    for (int i = 0; i < 4; i++) {
        int r = ty + 8 * i;
        t16[(size_t)(n0 + r) * K + k0 + tx] = __float2half_rn(t[tx][r]);
    }
}

// ---------------------------------------------------------------------------
// Tensor-core attention, no-max softmax, row sums via ones-MMA.
// CTA = (b, h, 128-query tile); 128 threads, 4 warps x 32 q rows; 2 CTAs/SM.
// KV chunks of 64; 3-stage cp.async pipeline, one sync per chunk.
// All single fp16: Q (pre-scaled in g_q16), K, P=ex2(S), V^T.
// ---------------------------------------------------------------------------
#define AT_ROWB  144
#define AT_QBYTES (128 * AT_ROWB)     // 18432
#define AT_TILEB  (64 * AT_ROWB)      // 9216
#define AT_STAGEB (2 * AT_TILEB)      // 18432 (K, V)
#define AT_SMEM_BYTES (AT_QBYTES + 3 * AT_STAGEB)   // 73728
#define ONES_H2 0x3C003C00u

__global__ __launch_bounds__(128, 2)
void attn_tc_kernel(const __half* __restrict__ q16,
                    const __half* __restrict__ kk, const __half* __restrict__ vT,
                    __half* __restrict__ wa16)
{
    extern __shared__ __align__(128) char smem[];
    const uint32_t smem_base = smem_to_u32(smem);
    const uint32_t qB  = smem_base;
    const uint32_t kvB = smem_base + AT_QBYTES;

    const int b  = blockIdx.z;
    const int h  = blockIdx.y;
    const int qt = blockIdx.x;            // 0..7 (128 queries each)
    const int tid = threadIdx.x;
    const int wid = tid >> 5;
    const int lane = tid & 31;

    const __half* q_base = q16 + (size_t)(b * NN + qt * 128) * DIM + h * HD;
    const __half* k_base = kk + (size_t)(b * NN) * DIM + h * HD;
    const __half* v_base = vT + (size_t)(b * DIM + h * HD) * NN;

    auto load_kv = [&](int kt, int st) {
        const uint32_t dst0 = kvB + st * AT_STAGEB;
#pragma unroll
        for (int i = 0; i < 8; i++) {
            const int idx = i * 128 + tid;   // 0..1023
            const int t = idx >> 9;          // 0 = K, 1 = V
            const int j = idx & 511;
            const int r = j >> 3;
            const int c = j & 7;
            const __half* src = (t == 0)
                ? k_base + (size_t)(kt * 64 + r) * DIM + c * 8
                : v_base + (size_t)r * NN + kt * 64 + c * 8;
            CP_ASYNC_16(dst0 + t * AT_TILEB + r * AT_ROWB + c * 16, src);
        }
    };

    // prologue: Q (group 0), KV chunk 0 (group 1), KV chunk 1 (group 2)
    {
#pragma unroll
        for (int i = 0; i < 8; i++) {
            int idx = i * 128 + tid;         // 0..1023
            int r = idx >> 3, c = idx & 7;
            CP_ASYNC_16(qB + r * AT_ROWB + c * 16, q_base + (size_t)r * DIM + c * 8);
        }
        CP_COMMIT();
    }
    load_kv(0, 0); CP_COMMIT();
    load_kv(1, 1); CP_COMMIT();

    const int qrow = wid * 32;
    const int lrow = lane & 15;
    const int lcol = lane >> 4;

    uint32_t qh[2][4][4];

    float oacc[2][8][4];
    float sumacc[2][4];
#pragma unroll
    for (int mf = 0; mf < 2; mf++) {
#pragma unroll
        for (int df = 0; df < 8; df++)
#pragma unroll
            for (int e = 0; e < 4; e++) oacc[mf][df][e] = 0.f;
#pragma unroll
        for (int e = 0; e < 4; e++) sumacc[mf][e] = 0.f;
    }

    for (int kt = 0; kt < NN / 64; kt++) {
        const int st = kt % 3;
        CP_WAIT1();
        __syncthreads();

        if (kt == 0) {
            // hoist Q fragments (loop-invariant)
#pragma unroll
            for (int ks = 0; ks < 4; ks++) {
                const uint32_t kboff = (ks * 2 + lcol) * 16;
#pragma unroll
                for (int mf = 0; mf < 2; mf++) {
                    uint32_t qoff = (qrow + mf * 16 + lrow) * AT_ROWB + kboff;
                    ldm_x4(qB + qoff, qh[mf][ks][0], qh[mf][ks][1],
                           qh[mf][ks][2], qh[mf][ks][3]);
                }
            }
        }

        const uint32_t kB = kvB + st * AT_STAGEB;
        const uint32_t vB = kB + AT_TILEB;

        // ---- S = Q @ K^T (log2 units) ----
        float sacc[2][8][4];
#pragma unroll
        for (int mf = 0; mf < 2; mf++)
#pragma unroll
            for (int nf = 0; nf < 8; nf++)
#pragma unroll
                for (int e = 0; e < 4; e++) sacc[mf][nf][e] = 0.f;

#pragma unroll
        for (int ks = 0; ks < 4; ks++) {
            const uint32_t kboff = (ks * 2 + lcol) * 16;
#pragma unroll
            for (int np = 0; np < 4; np++) {
                uint32_t roff = (np * 16 + lrow) * AT_ROWB + kboff;
                uint32_t kf[4];
                ldm_x4(kB + roff, kf[0], kf[1], kf[2], kf[3]);
#pragma unroll
                for (int mf = 0; mf < 2; mf++)
#pragma unroll
                    for (int sub = 0; sub < 2; sub++)
                        mma_f16(sacc[mf][np * 2 + sub],
                                qh[mf][ks][0], qh[mf][ks][1], qh[mf][ks][2],
                                qh[mf][ks][3], kf[sub], kf[sub + 2]);
            }
        }

        // ---- P = 2^S (fp16); O += P@V; rowsum += P@ones ----
#pragma unroll
        for (int kt2 = 0; kt2 < 4; kt2++) {
            uint32_t pa[2][4];
#pragma unroll
            for (int mf = 0; mf < 2; mf++) {
                float* s0 = sacc[mf][kt2 * 2];
                float* s1 = sacc[mf][kt2 * 2 + 1];
                pa[mf][0] = packh2(ex2f(s0[0]), ex2f(s0[1]));
                pa[mf][1] = packh2(ex2f(s0[2]), ex2f(s0[3]));
                pa[mf][2] = packh2(ex2f(s1[0]), ex2f(s1[1]));
                pa[mf][3] = packh2(ex2f(s1[2]), ex2f(s1[3]));
            }
            const uint32_t cboff = (kt2 * 2 + lcol) * 16;
#pragma unroll
            for (int dp = 0; dp < 4; dp++) {
                uint32_t roff = (dp * 16 + lrow) * AT_ROWB + cboff;
                uint32_t vf[4];
                ldm_x4(vB + roff, vf[0], vf[1], vf[2], vf[3]);
#pragma unroll
                for (int mf = 0; mf < 2; mf++)
#pragma unroll
                    for (int sub = 0; sub < 2; sub++)
                        mma_f16(oacc[mf][dp * 2 + sub],
                                pa[mf][0], pa[mf][1], pa[mf][2], pa[mf][3],
                                vf[sub], vf[sub + 2]);
            }
#pragma unroll
            for (int mf = 0; mf < 2; mf++)
                mma_f16(sumacc[mf], pa[mf][0], pa[mf][1], pa[mf][2], pa[mf][3],
                        ONES_H2, ONES_H2);
        }

        if (kt + 2 < NN / 64) load_kv(kt + 2, (kt + 2) % 3);
        CP_COMMIT();
    }

    // ---- Epilogue: normalize, store wa fp16 [B,N,DIM] ----
#pragma unroll
    for (int mf = 0; mf < 2; mf++) {
        const float inv0 = 1.f / sumacc[mf][0];
        const float inv1 = 1.f / sumacc[mf][2];
        const int row = b * NN + qt * 128 + qrow + mf * 16 + (lane >> 2);
#pragma unroll
        for (int df = 0; df < 8; df++) {
            const int col = h * HD + df * 8 + (lane & 3) * 2;
            *(uint32_t*)(wa16 + (size_t)row * DIM + col) =
                packh2(oacc[mf][df][0] * inv0, oacc[mf][df][1] * inv0);
            *(uint32_t*)(wa16 + (size_t)(row + 8) * DIM + col) =
                packh2(oacc[mf][df][2] * inv1, oacc[mf][df][3] * inv1);
        }
    }
}

// ---------------------------------------------------------------------------
extern "C" void kernel_launch(void* const* d_in, const int* in_sizes, int n_in,
                              void* d_out, int out_size)
{
    (void)in_sizes; (void)n_in; (void)out_size;
    const float* en    = (const float*)d_in[0];
    const float* dec   = (const float*)d_in[1];
    const float* Wkv   = (const float*)d_in[2];
    const float* bkv   = (const float*)d_in[3];
    const float* Wproj = (const float*)d_in[4];
    const float* bproj = (const float*)d_in[5];
    float* out = (float*)d_out;

    __half *en16, *q16, *wa16, *wkvt, *wpt, *kk, *vT;
    cudaGetSymbolAddress((void**)&en16, g_en16);
    cudaGetSymbolAddress((void**)&q16, g_q16);
    cudaGetSymbolAddress((void**)&wa16, g_wa16);
    cudaGetSymbolAddress((void**)&wkvt, g_Wkvt);
    cudaGetSymbolAddress((void**)&wpt, g_Wpt);
    cudaGetSymbolAddress((void**)&kk, g_k);
    cudaGetSymbolAddress((void**)&vT, g_vT);

    cudaFuncSetAttribute(gemm_kv_kernel,
                         cudaFuncAttributeMaxDynamicSharedMemorySize, GT_SMEM_BYTES);
    cudaFuncSetAttribute(gemm_out_kernel,
                         cudaFuncAttributeMaxDynamicSharedMemorySize, GT_SMEM_BYTES);
    cudaFuncSetAttribute(attn_tc_kernel,
                         cudaFuncAttributeMaxDynamicSharedMemorySize, AT_SMEM_BYTES);

    // 0) converts
    {
        int n4 = M_TOTAL * DIM / 4;
        conv16_kernel<<<n4 / 256, 256>>>((const float4*)en, (uint2*)en16, 1.0f, n4);
        conv16_kernel<<<n4 / 256, 256>>>((const float4*)dec, (uint2*)q16, QSCALE, n4);
    }
    tsplit_kernel<<<dim3(KV_N / 32, DIM / 32), dim3(32, 8)>>>(Wkv, wkvt, DIM, KV_N);
    tsplit_kernel<<<dim3(DIM / 32, DIM / 32), dim3(32, 8)>>>(Wproj, wpt, DIM, DIM);

    // 1) kv projection -> K fp16, V^T fp16
    gemm_kv_kernel<<<dim3(KV_N / 128, M_TOTAL / 128), 128, GT_SMEM_BYTES>>>(
        en16, wkvt, bkv, kk, vT);

    // 2) tensor-core attention -> wa fp16
    attn_tc_kernel<<<dim3(NN / 128, NH, BB), 128, AT_SMEM_BYTES>>>(
        q16, kk, vT, wa16);

    // 3) output projection
    gemm_out_kernel<<<dim3(DIM / 128, M_TOTAL / 128), 128, GT_SMEM_BYTES>>>(
        wa16, wpt, bproj, out);
}

// round 8
// speedup vs baseline: 6.6775x; 1.2343x over previous
#include <cuda_runtime.h>
#include <cuda_fp16.h>
#include <math.h>
#include <stdint.h>

// Problem constants
#define BB   8
#define NN   1024
#define DIM  768
#define NH   12
#define HD   64

#define M_TOTAL (BB*NN)          // 8192
#define KV_N    (2*DIM)          // 1536

// 0.125 * log2(e): folded into Q so exp(s*0.125) = 2^(S_acc)
#define QSCALE 0.180336880596349f

// ---------------------------------------------------------------------------
// Scratch (device globals)
// ---------------------------------------------------------------------------
__device__ __align__(256) __half g_en16[M_TOTAL * DIM];
__device__ __align__(256) __half g_q16[M_TOTAL * DIM];    // dec * QSCALE, fp16
__device__ __align__(256) __half g_wa16[M_TOTAL * DIM];
__device__ __align__(256) __half g_Wkvt[KV_N * DIM];      // [1536][768] (N,K)
__device__ __align__(256) __half g_Wpt[DIM * DIM];        // [768][768]  (N,K)
__device__ __align__(256) __half g_k[M_TOTAL * DIM];      // K [8192][768]
__device__ __align__(256) __half g_vT[BB * DIM * NN];     // V^T [B][768][1024]

// ---------------------------------------------------------------------------
// Low-level helpers
// ---------------------------------------------------------------------------
__device__ __forceinline__ uint32_t smem_to_u32(const void* smem_ptr) {
    uint32_t addr;
    asm("{ .reg .u64 tmp; cvta.to.shared.u64 tmp, %1; cvt.u32.u64 %0, tmp; }"
        : "=r"(addr) : "l"(smem_ptr));
    return addr;
}

#define CP_ASYNC_16(dst_u32, src_ptr) \
    asm volatile("cp.async.cg.shared.global [%0], [%1], 16;" \
                 :: "r"(dst_u32), "l"(src_ptr))
#define CP_COMMIT() asm volatile("cp.async.commit_group;" ::: "memory")
#define CP_WAIT1()  asm volatile("cp.async.wait_group 1;" ::: "memory")

__device__ __forceinline__ void ldm_x4(uint32_t addr, uint32_t& r0, uint32_t& r1,
                                       uint32_t& r2, uint32_t& r3) {
    asm volatile("ldmatrix.sync.aligned.m8n8.x4.shared.b16 {%0,%1,%2,%3}, [%4];"
                 : "=r"(r0), "=r"(r1), "=r"(r2), "=r"(r3) : "r"(addr));
}

__device__ __forceinline__ void mma_f16(float* c, uint32_t a0, uint32_t a1,
                                        uint32_t a2, uint32_t a3,
                                        uint32_t b0, uint32_t b1) {
    asm volatile(
        "mma.sync.aligned.m16n8k16.row.col.f32.f16.f16.f32 "
        "{%0,%1,%2,%3}, {%4,%5,%6,%7}, {%8,%9}, {%0,%1,%2,%3};"
        : "+f"(c[0]), "+f"(c[1]), "+f"(c[2]), "+f"(c[3])
        : "r"(a0), "r"(a1), "r"(a2), "r"(a3), "r"(b0), "r"(b1));
}

__device__ __forceinline__ float ex2f(float x) {
    float y;
    asm("ex2.approx.f32 %0, %1;" : "=f"(y) : "f"(x));
    return y;
}

__device__ __forceinline__ uint32_t packh2(float lo, float hi) {
    half2 h = __floats2half2_rn(lo, hi);
    return *reinterpret_cast<uint32_t*>(&h);
}

// Full-width 128B rows (64 halves), SW128-style 16B-chunk swizzle.
// chunk c in 0..7, row r: phys = c ^ (r & 7)  -> conflict-free stores + ldmatrix
__device__ __forceinline__ uint32_t row128_addr(uint32_t base, int r, int c16) {
    return base + r * 128 + ((c16 ^ (r & 7)) << 4);
}

// ---------------------------------------------------------------------------
// GEMM: C tile 128x128 = A[128,K] @ B^T[128,K]  (single fp16, fp32 acc)
// 128 threads, 4 warps (2m x 2n), warp tile 64x64. BK=64 -> one barrier per
// 64-K chunk (128 MMAs/warp per epoch). 3-stage cp.async pipeline, 2 CTAs/SM.
// Tensor = 128 rows * 128 B = 16384 B; stage = A+B = 32768 B; 3 stages = 96 KB.
// ---------------------------------------------------------------------------
#define GT_TENSOR_B   16384
#define GT_STAGE_B    32768
#define GT_SMEM_BYTES (3 * GT_STAGE_B)   // 98304

template <typename EpilogueFn>
__device__ __forceinline__ void gemm_tile(
    const __half* A, const __half* B, int K, int m0, int n0,
    uint32_t smem_base, EpilogueFn epi)
{
    const int tid  = threadIdx.x;
    const int lane = tid & 31;

    const __half* Abase = A + (size_t)m0 * K;
    const __half* Bbase = B + (size_t)n0 * K;

    auto load_chunk = [&](int chunk, int s) {
        const int k0 = chunk * 64;
        const uint32_t sbase = smem_base + s * GT_STAGE_B;
#pragma unroll
        for (int i = 0; i < 16; i++) {
            int idx = i * 128 + tid;       // 0..2047
            int t = idx >> 10;             // 0 = A, 1 = B
            int j = idx & 1023;
            int r = j >> 3, c = j & 7;
            const __half* src = (t == 0 ? Abase : Bbase) + (size_t)r * K + k0 + c * 8;
            CP_ASYNC_16(row128_addr(sbase + t * GT_TENSOR_B, r, c), src);
        }
    };

    float acc[4][8][4];
#pragma unroll
    for (int mf = 0; mf < 4; mf++)
#pragma unroll
        for (int nf = 0; nf < 8; nf++)
#pragma unroll
            for (int e = 0; e < 4; e++) acc[mf][nf][e] = 0.f;

    const int wid = tid >> 5;
    const int wm  = wid & 1;           // 2 warps in m (64 rows each)
    const int wn  = wid >> 1;          // 2 warps in n (64 cols each)
    const int i8   = lane & 7;
    const int quad = lane >> 3;
    const int qr   = (quad & 1) << 3;
    const int qc   = quad >> 1;

    const int NCHUNK = K >> 6;         // K/64

    load_chunk(0, 0); CP_COMMIT();
    load_chunk(1, 1); CP_COMMIT();

    for (int ch = 0; ch < NCHUNK; ch++) {
        const int s = ch % 3;
        CP_WAIT1();
        __syncthreads();

        const uint32_t aB = smem_base + s * GT_STAGE_B;
        const uint32_t bB = aB + GT_TENSOR_B;

#pragma unroll
        for (int kf = 0; kf < 4; kf++) {
            const int kb = kf * 2 + qc;    // 16B-chunk index 0..7
            uint32_t af[4][4];
#pragma unroll
            for (int mf = 0; mf < 4; mf++) {
                int r = wm * 64 + mf * 16 + i8 + qr;
                ldm_x4(row128_addr(aB, r, kb), af[mf][0], af[mf][1], af[mf][2], af[mf][3]);
            }
            uint32_t bf[4][4];
#pragma unroll
            for (int nf2 = 0; nf2 < 4; nf2++) {
                int r = wn * 64 + nf2 * 16 + i8 + qr;
                ldm_x4(row128_addr(bB, r, kb), bf[nf2][0], bf[nf2][1], bf[nf2][2], bf[nf2][3]);
            }
#pragma unroll
            for (int mf = 0; mf < 4; mf++)
#pragma unroll
                for (int nf = 0; nf < 8; nf++) {
                    const int nf2 = nf >> 1, od = nf & 1;
                    mma_f16(acc[mf][nf], af[mf][0], af[mf][1], af[mf][2], af[mf][3],
                            bf[nf2][od], bf[nf2][od + 2]);
                }
        }

        if (ch + 2 < NCHUNK) load_chunk(ch + 2, (ch + 2) % 3);
        CP_COMMIT();   // empty group when no load: keeps wait counting exact
    }
    epi(acc, wm, wn, lane);
}

// GEMM1: kv projection -> K fp16 ([B*N,768]) and V fp16 transposed
__global__ __launch_bounds__(128, 2)
void gemm_kv_kernel(const __half* __restrict__ A, const __half* __restrict__ B,
                    const float* __restrict__ bias,
                    __half* __restrict__ kk, __half* __restrict__ vT)
{
    extern __shared__ __align__(128) char smem[];
    const uint32_t smem_base = smem_to_u32(smem);
    const int m0 = blockIdx.y * 128;
    const int n0 = blockIdx.x * 128;
    const bool isV = (n0 >= DIM);

    gemm_tile(A, B, DIM, m0, n0, smem_base,
        [&](float acc[4][8][4], int wm, int wn, int lane) {
#pragma unroll
            for (int mf = 0; mf < 4; mf++) {
                const int r0 = m0 + wm * 64 + mf * 16 + (lane >> 2);
#pragma unroll
                for (int nf = 0; nf < 8; nf++) {
                    const int col = n0 + wn * 64 + nf * 8 + (lane & 3) * 2;
                    float2 bv = *(const float2*)(bias + col);
                    __half h0 = __float2half_rn(acc[mf][nf][0] + bv.x);
                    __half h1 = __float2half_rn(acc[mf][nf][1] + bv.y);
                    __half h2 = __float2half_rn(acc[mf][nf][2] + bv.x);
                    __half h3 = __float2half_rn(acc[mf][nf][3] + bv.y);
                    if (!isV) {
                        *(uint32_t*)(kk + (size_t)r0 * DIM + col) =
                            ((uint32_t)*(uint16_t*)&h1 << 16) | *(uint16_t*)&h0;
                        *(uint32_t*)(kk + (size_t)(r0 + 8) * DIM + col) =
                            ((uint32_t)*(uint16_t*)&h3 << 16) | *(uint16_t*)&h2;
                    } else {
                        const int d = col - DIM;
                        const int b = r0 >> 10, seq = r0 & 1023;
                        size_t o00 = ((size_t)(b * DIM + d)) * NN + seq;
                        size_t o10 = o00 + NN;          // d+1
                        vT[o00] = h0;      vT[o10] = h1;
                        vT[o00 + 8] = h2;  vT[o10 + 8] = h3;   // seq+8
                    }
                }
            }
        });
}

// GEMM2: output projection, fp32 out + bias
__global__ __launch_bounds__(128, 2)
void gemm_out_kernel(const __half* __restrict__ A, const __half* __restrict__ B,
                     const float* __restrict__ bias, float* __restrict__ C)
{
    extern __shared__ __align__(128) char smem[];
    const uint32_t smem_base = smem_to_u32(smem);
    const int m0 = blockIdx.y * 128;
    const int n0 = blockIdx.x * 128;

    gemm_tile(A, B, DIM, m0, n0, smem_base,
        [&](float acc[4][8][4], int wm, int wn, int lane) {
#pragma unroll
            for (int mf = 0; mf < 4; mf++) {
                const int r0 = m0 + wm * 64 + mf * 16 + (lane >> 2);
#pragma unroll
                for (int nf = 0; nf < 8; nf++) {
                    const int col = n0 + wn * 64 + nf * 8 + (lane & 3) * 2;
                    float2 bv = *(const float2*)(bias + col);
                    *(float2*)(C + (size_t)r0 * DIM + col) =
                        make_float2(acc[mf][nf][0] + bv.x, acc[mf][nf][1] + bv.y);
                    *(float2*)(C + (size_t)(r0 + 8) * DIM + col) =
                        make_float2(acc[mf][nf][2] + bv.x, acc[mf][nf][3] + bv.y);
                }
            }
        });
}

// ---------------------------------------------------------------------------
// fp32 -> fp16 convert with scale; weight transpose -> fp16
// ---------------------------------------------------------------------------
__global__ __launch_bounds__(256)
void conv16_kernel(const float4* __restrict__ x, uint2* __restrict__ o,
                   float scale, int n4)
{
    int i = blockIdx.x * blockDim.x + threadIdx.x;
    if (i >= n4) return;
    float4 v = x[i];
    o[i] = make_uint2(packh2(v.x * scale, v.y * scale),
                      packh2(v.z * scale, v.w * scale));
}

__global__ __launch_bounds__(256)
void tsplit_kernel(const float* __restrict__ W, __half* __restrict__ t16,
                   int K, int N)
{
    __shared__ float t[32][33];
    const int n0 = blockIdx.x * 32, k0 = blockIdx.y * 32;
    const int tx = threadIdx.x, ty = threadIdx.y;
#pragma unroll
    for (int i = 0; i < 4; i++)
        t[ty + 8 * i][tx] = W[(size_t)(k0 + ty + 8 * i) * N + n0 + tx];
    __syncthreads();
#pragma unroll
    for (int i = 0; i < 4; i++) {
        int r = ty + 8 * i;
        t16[(size_t)(n0 + r) * K + k0 + tx] = __float2half_rn(t[tx][r]);
    }
}

// ---------------------------------------------------------------------------
// Tensor-core attention, no-max softmax, row sums via ones-MMA.
// CTA = (b, h, 128-query tile); 128 threads, 4 warps x 32 q rows; 2 CTAs/SM.
// KV chunks of 64 rows; 3-stage cp.async pipeline, one sync per chunk.
// Full 128B rows (HD = 64 halves) with XOR swizzle — no padding waste.
// ---------------------------------------------------------------------------
#define AT_QBYTES (128 * 128)         // 16384
#define AT_TILEB  (64 * 128)          // 8192
#define AT_STAGEB (2 * AT_TILEB)      // 16384 (K, V)
#define AT_SMEM_BYTES (AT_QBYTES + 3 * AT_STAGEB)   // 65536
#define ONES_H2 0x3C003C00u

__global__ __launch_bounds__(128, 2)
void attn_tc_kernel(const __half* __restrict__ q16,
                    const __half* __restrict__ kk, const __half* __restrict__ vT,
                    __half* __restrict__ wa16)
{
    extern __shared__ __align__(128) char smem[];
    const uint32_t smem_base = smem_to_u32(smem);
    const uint32_t qB  = smem_base;
    const uint32_t kvB = smem_base + AT_QBYTES;

    const int b  = blockIdx.z;
    const int h  = blockIdx.y;
    const int qt = blockIdx.x;            // 0..7 (128 queries each)
    const int tid = threadIdx.x;
    const int wid = tid >> 5;
    const int lane = tid & 31;

    const __half* q_base = q16 + (size_t)(b * NN + qt * 128) * DIM + h * HD;
    const __half* k_base = kk + (size_t)(b * NN) * DIM + h * HD;
    const __half* v_base = vT + (size_t)(b * DIM + h * HD) * NN;

    auto load_kv = [&](int kt, int st) {
        const uint32_t dst0 = kvB + st * AT_STAGEB;
#pragma unroll
        for (int i = 0; i < 8; i++) {
            const int idx = i * 128 + tid;   // 0..1023
            const int t = idx >> 9;          // 0 = K, 1 = V
            const int j = idx & 511;
            const int r = j >> 3;
            const int c = j & 7;
            const __half* src = (t == 0)
                ? k_base + (size_t)(kt * 64 + r) * DIM + c * 8
                : v_base + (size_t)r * NN + kt * 64 + c * 8;
            CP_ASYNC_16(row128_addr(dst0 + t * AT_TILEB, r, c), src);
        }
    };

    // prologue: Q (group 0), KV chunk 0 (group 1), KV chunk 1 (group 2)
    {
#pragma unroll
        for (int i = 0; i < 8; i++) {
            int idx = i * 128 + tid;         // 0..1023
            int r = idx >> 3, c = idx & 7;
            CP_ASYNC_16(row128_addr(qB, r, c), q_base + (size_t)r * DIM + c * 8);
        }
        CP_COMMIT();
    }
    load_kv(0, 0); CP_COMMIT();
    load_kv(1, 1); CP_COMMIT();

    const int qrow = wid * 32;
    const int lrow = lane & 15;
    const int lcol = lane >> 4;

    uint32_t qh[2][4][4];

    float oacc[2][8][4];
    float sumacc[2][4];
#pragma unroll
    for (int mf = 0; mf < 2; mf++) {
#pragma unroll
        for (int df = 0; df < 8; df++)
#pragma unroll
            for (int e = 0; e < 4; e++) oacc[mf][df][e] = 0.f;
#pragma unroll
        for (int e = 0; e < 4; e++) sumacc[mf][e] = 0.f;
    }

    for (int kt = 0; kt < NN / 64; kt++) {
        const int st = kt % 3;
        CP_WAIT1();
        __syncthreads();

        if (kt == 0) {
            // hoist Q fragments (loop-invariant)
#pragma unroll
            for (int ks = 0; ks < 4; ks++) {
                const int kb = ks * 2 + lcol;
#pragma unroll
                for (int mf = 0; mf < 2; mf++) {
                    int r = qrow + mf * 16 + lrow;
                    ldm_x4(row128_addr(qB, r, kb), qh[mf][ks][0], qh[mf][ks][1],
                           qh[mf][ks][2], qh[mf][ks][3]);
                }
            }
        }

        const uint32_t kB = kvB + st * AT_STAGEB;
        const uint32_t vB = kB + AT_TILEB;

        // ---- S = Q @ K^T (log2 units) ----
        float sacc[2][8][4];
#pragma unroll
        for (int mf = 0; mf < 2; mf++)
#pragma unroll
            for (int nf = 0; nf < 8; nf++)
#pragma unroll
                for (int e = 0; e < 4; e++) sacc[mf][nf][e] = 0.f;

#pragma unroll
        for (int ks = 0; ks < 4; ks++) {
            const int kb = ks * 2 + lcol;
#pragma unroll
            for (int np = 0; np < 4; np++) {
                int r = np * 16 + lrow;
                uint32_t kf[4];
                ldm_x4(row128_addr(kB, r, kb), kf[0], kf[1], kf[2], kf[3]);
#pragma unroll
                for (int mf = 0; mf < 2; mf++)
#pragma unroll
                    for (int sub = 0; sub < 2; sub++)
                        mma_f16(sacc[mf][np * 2 + sub],
                                qh[mf][ks][0], qh[mf][ks][1], qh[mf][ks][2],
                                qh[mf][ks][3], kf[sub], kf[sub + 2]);
            }
        }

        // ---- P = 2^S (fp16); O += P@V; rowsum += P@ones ----
#pragma unroll
        for (int kt2 = 0; kt2 < 4; kt2++) {
            uint32_t pa[2][4];
#pragma unroll
            for (int mf = 0; mf < 2; mf++) {
                float* s0 = sacc[mf][kt2 * 2];
                float* s1 = sacc[mf][kt2 * 2 + 1];
                pa[mf][0] = packh2(ex2f(s0[0]), ex2f(s0[1]));
                pa[mf][1] = packh2(ex2f(s0[2]), ex2f(s0[3]));
                pa[mf][2] = packh2(ex2f(s1[0]), ex2f(s1[1]));
                pa[mf][3] = packh2(ex2f(s1[2]), ex2f(s1[3]));
            }
            const int cb = kt2 * 2 + lcol;
#pragma unroll
            for (int dp = 0; dp < 4; dp++) {
                int r = dp * 16 + lrow;
                uint32_t vf[4];
                ldm_x4(row128_addr(vB, r, cb), vf[0], vf[1], vf[2], vf[3]);
#pragma unroll
                for (int mf = 0; mf < 2; mf++)
#pragma unroll
                    for (int sub = 0; sub < 2; sub++)
                        mma_f16(oacc[mf][dp * 2 + sub],
                                pa[mf][0], pa[mf][1], pa[mf][2], pa[mf][3],
                                vf[sub], vf[sub + 2]);
            }
#pragma unroll
            for (int mf = 0; mf < 2; mf++)
                mma_f16(sumacc[mf], pa[mf][0], pa[mf][1], pa[mf][2], pa[mf][3],
                        ONES_H2, ONES_H2);
        }

        if (kt + 2 < NN / 64) load_kv(kt + 2, (kt + 2) % 3);
        CP_COMMIT();
    }

    // ---- Epilogue: normalize, store wa fp16 [B,N,DIM] ----
#pragma unroll
    for (int mf = 0; mf < 2; mf++) {
        const float inv0 = 1.f / sumacc[mf][0];
        const float inv1 = 1.f / sumacc[mf][2];
        const int row = b * NN + qt * 128 + qrow + mf * 16 + (lane >> 2);
#pragma unroll
        for (int df = 0; df < 8; df++) {
            const int col = h * HD + df * 8 + (lane & 3) * 2;
            *(uint32_t*)(wa16 + (size_t)row * DIM + col) =
                packh2(oacc[mf][df][0] * inv0, oacc[mf][df][1] * inv0);
            *(uint32_t*)(wa16 + (size_t)(row + 8) * DIM + col) =
                packh2(oacc[mf][df][2] * inv1, oacc[mf][df][3] * inv1);
        }
    }
}

// ---------------------------------------------------------------------------
extern "C" void kernel_launch(void* const* d_in, const int* in_sizes, int n_in,
                              void* d_out, int out_size)
{
    (void)in_sizes; (void)n_in; (void)out_size;
    const float* en    = (const float*)d_in[0];
    const float* dec   = (const float*)d_in[1];
    const float* Wkv   = (const float*)d_in[2];
    const float* bkv   = (const float*)d_in[3];
    const float* Wproj = (const float*)d_in[4];
    const float* bproj = (const float*)d_in[5];
    float* out = (float*)d_out;

    __half *en16, *q16, *wa16, *wkvt, *wpt, *kk, *vT;
    cudaGetSymbolAddress((void**)&en16, g_en16);
    cudaGetSymbolAddress((void**)&q16, g_q16);
    cudaGetSymbolAddress((void**)&wa16, g_wa16);
    cudaGetSymbolAddress((void**)&wkvt, g_Wkvt);
    cudaGetSymbolAddress((void**)&wpt, g_Wpt);
    cudaGetSymbolAddress((void**)&kk, g_k);
    cudaGetSymbolAddress((void**)&vT, g_vT);

    cudaFuncSetAttribute(gemm_kv_kernel,
                         cudaFuncAttributeMaxDynamicSharedMemorySize, GT_SMEM_BYTES);
    cudaFuncSetAttribute(gemm_out_kernel,
                         cudaFuncAttributeMaxDynamicSharedMemorySize, GT_SMEM_BYTES);
    cudaFuncSetAttribute(attn_tc_kernel,
                         cudaFuncAttributeMaxDynamicSharedMemorySize, AT_SMEM_BYTES);

    // 0) converts
    {
        int n4 = M_TOTAL * DIM / 4;
        conv16_kernel<<<n4 / 256, 256>>>((const float4*)en, (uint2*)en16, 1.0f, n4);
        conv16_kernel<<<n4 / 256, 256>>>((const float4*)dec, (uint2*)q16, QSCALE, n4);
    }
    tsplit_kernel<<<dim3(KV_N / 32, DIM / 32), dim3(32, 8)>>>(Wkv, wkvt, DIM, KV_N);
    tsplit_kernel<<<dim3(DIM / 32, DIM / 32), dim3(32, 8)>>>(Wproj, wpt, DIM, DIM);

    // 1) kv projection -> K fp16, V^T fp16
    gemm_kv_kernel<<<dim3(KV_N / 128, M_TOTAL / 128), 128, GT_SMEM_BYTES>>>(
        en16, wkvt, bkv, kk, vT);

    // 2) tensor-core attention -> wa fp16
    attn_tc_kernel<<<dim3(NN / 128, NH, BB), 128, AT_SMEM_BYTES>>>(
        q16, kk, vT, wa16);

    // 3) output projection
    gemm_out_kernel<<<dim3(DIM / 128, M_TOTAL / 128), 128, GT_SMEM_BYTES>>>(
        wa16, wpt, bproj, out);
}